// round 1
// baseline (speedup 1.0000x reference)
#include <cuda_runtime.h>
#include <math.h>

// Shapes (fixed by the problem):
//   x:      [16, 256, 64, 64]  -> [b=16][c=256][n=4096]
//   w_qkv:  [768, 256] row-major
//   w_out:  [256, 256] row-major
//   gamma, beta: [256]
//   out:    [16, 256, 4096]
//
// Pipeline:
//   1) qkv = W_qkv @ X per batch (GEMM 768x4096x256), elu+1 on q,k rows -> scratch
//   2) s[b,c] = (sum_n kk*v) / max(sum_n kk, 1e-6)
//   3) out2 = (W_out * s_col) @ qk  (GEMM 256x4096x256), fused channel-LayerNorm

#define B_   16
#define C_   256
#define N_   4096
#define M1_  768

// 192 MB scratch: [b][768][4096] = qk (rows 0..255), kk (256..511), v (512..767)
__device__ float g_scratch[50331648];   // 16*768*4096
__device__ float g_s[4096];             // [b][c] per-channel scale

// ---------------------------------------------------------------------------
// Kernel A: QKV GEMM, 128x128 tile, K-step 16, 256 threads, 8x8 per thread.
// Epilogue: elu(x)+1 on rows < 512 (q and k), raw for v. Stores to g_scratch.
// ---------------------------------------------------------------------------
__global__ __launch_bounds__(256) void k_gemm_qkv(const float* __restrict__ x,
                                                  const float* __restrict__ w) {
    __shared__ float As[16][128];
    __shared__ float Bs[16][128];
    const int tid = threadIdx.x;
    const int tn = tid & 15;       // 16 threads along N, 8 cols each
    const int tm = tid >> 4;       // 16 threads along M, 8 rows each
    const int n0 = blockIdx.x * 128;
    const int m0 = blockIdx.y * 128;
    const int b  = blockIdx.z;
    const float* X = x + (size_t)b * C_ * N_;

    float acc[8][8];
    #pragma unroll
    for (int i = 0; i < 8; ++i)
        #pragma unroll
        for (int j = 0; j < 8; ++j) acc[i][j] = 0.f;

    for (int kt = 0; kt < 256; kt += 16) {
        // A tile: 128 rows x 16 k, stored transposed As[k][m]
        #pragma unroll
        for (int it = 0; it < 2; ++it) {
            int f   = tid + it * 256;        // 512 float4 total
            int row = f >> 2;
            int k4  = (f & 3) * 4;
            float4 v = *reinterpret_cast<const float4*>(
                w + (size_t)(m0 + row) * 256 + kt + k4);
            As[k4 + 0][row] = v.x;
            As[k4 + 1][row] = v.y;
            As[k4 + 2][row] = v.z;
            As[k4 + 3][row] = v.w;
        }
        // B tile: 16 k x 128 n
        #pragma unroll
        for (int it = 0; it < 2; ++it) {
            int f   = tid + it * 256;        // 512 float4 total
            int row = f >> 5;
            int c4  = (f & 31) * 4;
            *reinterpret_cast<float4*>(&Bs[row][c4]) =
                *reinterpret_cast<const float4*>(X + (size_t)(kt + row) * N_ + n0 + c4);
        }
        __syncthreads();

        #pragma unroll
        for (int k = 0; k < 16; ++k) {
            float a[8], bb[8];
            #pragma unroll
            for (int i = 0; i < 8; ++i) a[i] = As[k][tm * 8 + i];
            #pragma unroll
            for (int j = 0; j < 8; ++j) bb[j] = Bs[k][tn * 8 + j];
            #pragma unroll
            for (int i = 0; i < 8; ++i)
                #pragma unroll
                for (int j = 0; j < 8; ++j)
                    acc[i][j] = fmaf(a[i], bb[j], acc[i][j]);
        }
        __syncthreads();
    }

    // Epilogue: elu+1 on q,k rows; store
    #pragma unroll
    for (int i = 0; i < 8; ++i) {
        int r = m0 + tm * 8 + i;
        bool el = (r < 512);
        float vals[8];
        #pragma unroll
        for (int j = 0; j < 8; ++j) {
            float v = acc[i][j];
            if (el) v = (v > 0.f) ? (v + 1.f) : expf(v);
            vals[j] = v;
        }
        float* dst = &g_scratch[((size_t)b * M1_ + r) * N_ + n0 + tn * 8];
        *reinterpret_cast<float4*>(dst)     = make_float4(vals[0], vals[1], vals[2], vals[3]);
        *reinterpret_cast<float4*>(dst + 4) = make_float4(vals[4], vals[5], vals[6], vals[7]);
    }
}

// ---------------------------------------------------------------------------
// Kernel B: per (b, c) channel, reduce kv = sum_n kk*v, denom = sum_n kk,
// store s = kv / max(denom, 1e-6)
// ---------------------------------------------------------------------------
__global__ __launch_bounds__(256) void k_reduce() {
    const int c = blockIdx.x;
    const int b = blockIdx.y;
    const float* kk = &g_scratch[((size_t)b * M1_ + 256 + c) * N_];
    const float* vv = &g_scratch[((size_t)b * M1_ + 512 + c) * N_];
    float skv = 0.f, sk = 0.f;
    for (int i = threadIdx.x; i < N_; i += 256) {
        float kval = kk[i];
        skv = fmaf(kval, vv[i], skv);
        sk += kval;
    }
    #pragma unroll
    for (int o = 16; o > 0; o >>= 1) {
        skv += __shfl_xor_sync(0xFFFFFFFFu, skv, o);
        sk  += __shfl_xor_sync(0xFFFFFFFFu, sk, o);
    }
    __shared__ float s1[8], s2[8];
    int w = threadIdx.x >> 5, l = threadIdx.x & 31;
    if (l == 0) { s1[w] = skv; s2[w] = sk; }
    __syncthreads();
    if (threadIdx.x == 0) {
        float a = 0.f, d = 0.f;
        #pragma unroll
        for (int i = 0; i < 8; ++i) { a += s1[i]; d += s2[i]; }
        g_s[b * C_ + c] = a / fmaxf(d, 1e-6f);
    }
}

// ---------------------------------------------------------------------------
// Kernel C: out GEMM (256 x 64 tile = ALL output channels per pixel tile) with
// per-batch scale folded into W_out columns, fused channel LayerNorm epilogue.
// 256 threads: tm in [0,32) owns 8 rows, tn in [0,8) owns 8 cols.
// ---------------------------------------------------------------------------
__global__ __launch_bounds__(256) void k_gemm_out_ln(const float* __restrict__ w_out,
                                                     const float* __restrict__ gamma,
                                                     const float* __restrict__ beta,
                                                     float* __restrict__ out) {
    __shared__ float As[16][256];
    __shared__ float Bs[16][64];
    __shared__ float s_sm[256], g_sm[256], be_sm[256];
    __shared__ float red_s[32][64];
    __shared__ float red_q[32][64];
    __shared__ float mu_s[64], rs_s[64];

    const int tid = threadIdx.x;
    const int tn = tid & 7;
    const int tm = tid >> 3;
    const int n0 = blockIdx.x * 64;
    const int b  = blockIdx.y;

    s_sm[tid]  = g_s[b * C_ + tid];
    g_sm[tid]  = gamma[tid];
    be_sm[tid] = beta[tid];
    __syncthreads();

    float acc[8][8];
    #pragma unroll
    for (int i = 0; i < 8; ++i)
        #pragma unroll
        for (int j = 0; j < 8; ++j) acc[i][j] = 0.f;

    for (int kt = 0; kt < 256; kt += 16) {
        // A tile: 256 rows x 16 k, scaled by s (per-column c), stored As[k][m]
        #pragma unroll
        for (int it = 0; it < 4; ++it) {
            int f   = tid + it * 256;        // 1024 float4 total
            int row = f >> 2;
            int k4  = (f & 3) * 4;
            float4 v = *reinterpret_cast<const float4*>(
                w_out + (size_t)row * 256 + kt + k4);
            As[k4 + 0][row] = v.x * s_sm[kt + k4 + 0];
            As[k4 + 1][row] = v.y * s_sm[kt + k4 + 1];
            As[k4 + 2][row] = v.z * s_sm[kt + k4 + 2];
            As[k4 + 3][row] = v.w * s_sm[kt + k4 + 3];
        }
        // B tile: 16 k x 64 n (qk rows of scratch)
        {
            int f   = tid;                   // 256 float4 total
            int row = f >> 4;
            int c4  = (f & 15) * 4;
            *reinterpret_cast<float4*>(&Bs[row][c4]) =
                *reinterpret_cast<const float4*>(
                    &g_scratch[((size_t)b * M1_ + kt + row) * N_ + n0 + c4]);
        }
        __syncthreads();

        #pragma unroll
        for (int k = 0; k < 16; ++k) {
            float a[8], bb[8];
            #pragma unroll
            for (int i = 0; i < 8; ++i) a[i] = As[k][tm * 8 + i];
            #pragma unroll
            for (int j = 0; j < 8; ++j) bb[j] = Bs[k][tn * 8 + j];
            #pragma unroll
            for (int i = 0; i < 8; ++i)
                #pragma unroll
                for (int j = 0; j < 8; ++j)
                    acc[i][j] = fmaf(a[i], bb[j], acc[i][j]);
        }
        __syncthreads();
    }

    // --- fused LayerNorm over the 256 channels this block fully owns ---
    #pragma unroll
    for (int j = 0; j < 8; ++j) {
        float s = 0.f, q = 0.f;
        #pragma unroll
        for (int i = 0; i < 8; ++i) {
            s += acc[i][j];
            q = fmaf(acc[i][j], acc[i][j], q);
        }
        red_s[tm][tn * 8 + j] = s;
        red_q[tm][tn * 8 + j] = q;
    }
    __syncthreads();
    if (tid < 64) {
        float s = 0.f, q = 0.f;
        #pragma unroll
        for (int t = 0; t < 32; ++t) { s += red_s[t][tid]; q += red_q[t][tid]; }
        float mu  = s * (1.f / 256.f);
        float var = q * (1.f / 256.f) - mu * mu;
        mu_s[tid] = mu;
        rs_s[tid] = rsqrtf(var + 1e-5f);
    }
    __syncthreads();

    #pragma unroll
    for (int i = 0; i < 8; ++i) {
        int r = tm * 8 + i;
        float ga = g_sm[r], be = be_sm[r];
        float vals[8];
        #pragma unroll
        for (int j = 0; j < 8; ++j) {
            int col = tn * 8 + j;
            vals[j] = (acc[i][j] - mu_s[col]) * rs_s[col] * ga + be;
        }
        float* dst = out + ((size_t)b * C_ + r) * N_ + n0 + tn * 8;
        *reinterpret_cast<float4*>(dst)     = make_float4(vals[0], vals[1], vals[2], vals[3]);
        *reinterpret_cast<float4*>(dst + 4) = make_float4(vals[4], vals[5], vals[6], vals[7]);
    }
}

// ---------------------------------------------------------------------------
extern "C" void kernel_launch(void* const* d_in, const int* in_sizes, int n_in,
                              void* d_out, int out_size) {
    const float* x      = (const float*)d_in[0];
    const float* w_qkv  = (const float*)d_in[1];
    const float* w_out  = (const float*)d_in[2];
    const float* gamma  = (const float*)d_in[3];
    const float* beta   = (const float*)d_in[4];
    float* out = (float*)d_out;

    k_gemm_qkv   <<<dim3(32, 6, 16), 256>>>(x, w_qkv);
    k_reduce     <<<dim3(256, 16),   256>>>();
    k_gemm_out_ln<<<dim3(64, 16),    256>>>(w_out, gamma, beta, out);
}

// round 5
// speedup vs baseline: 1.0558x; 1.0558x over previous
#include <cuda_runtime.h>
#include <cuda_bf16.h>
#include <math.h>
#include <stdint.h>

// Shapes: x [16,256,4096], w_qkv [768,256], w_out [256,256], gamma/beta [256]
#define B_ 16
#define C_ 256
#define N_ 4096

// scratch: 3 x 64MiB fp32 planes (same total as the passing round-1 kernel)
__device__ float g_QK[16777216];   // elu(q)+1
__device__ float g_KK[16777216];   // elu(k)+1
__device__ float g_V [16777216];   // v
__device__ float g_s [4096];       // per (b,c) scale

// ---------------------------------------------------------------- helpers
__device__ __forceinline__ uint32_t smem_u32(const void* p) {
    return (uint32_t)__cvta_generic_to_shared(p);
}
__device__ __forceinline__ void ldsm_x4(uint32_t& r0, uint32_t& r1, uint32_t& r2, uint32_t& r3, uint32_t a) {
    asm volatile("ldmatrix.sync.aligned.m8n8.x4.shared.b16 {%0,%1,%2,%3}, [%4];"
                 : "=r"(r0), "=r"(r1), "=r"(r2), "=r"(r3) : "r"(a));
}
__device__ __forceinline__ void ldsm_x4t(uint32_t& r0, uint32_t& r1, uint32_t& r2, uint32_t& r3, uint32_t a) {
    asm volatile("ldmatrix.sync.aligned.m8n8.x4.trans.shared.b16 {%0,%1,%2,%3}, [%4];"
                 : "=r"(r0), "=r"(r1), "=r"(r2), "=r"(r3) : "r"(a));
}
__device__ __forceinline__ void mma_bf16(float& d0, float& d1, float& d2, float& d3,
                                         uint32_t a0, uint32_t a1, uint32_t a2, uint32_t a3,
                                         uint32_t b0, uint32_t b1) {
    asm volatile("mma.sync.aligned.m16n8k16.row.col.f32.bf16.bf16.f32 "
                 "{%0,%1,%2,%3},{%4,%5,%6,%7},{%8,%9},{%0,%1,%2,%3};"
                 : "+f"(d0), "+f"(d1), "+f"(d2), "+f"(d3)
                 : "r"(a0), "r"(a1), "r"(a2), "r"(a3), "r"(b0), "r"(b1));
}
__device__ __forceinline__ float elu1(float v) { return v > 0.f ? v + 1.f : expf(v); }

// 3-split mma: d += ah*bh + ah*bl + al*bh
#define MMA3(ACC, AH, AL, BH0, BH1, BL0, BL1)                                   \
    mma_bf16(ACC[0], ACC[1], ACC[2], ACC[3],                                    \
             AH[0], AH[1], AH[2], AH[3], BH0, BH1);                             \
    mma_bf16(ACC[0], ACC[1], ACC[2], ACC[3],                                    \
             AH[0], AH[1], AH[2], AH[3], BL0, BL1);                             \
    mma_bf16(ACC[0], ACC[1], ACC[2], ACC[3],                                    \
             AL[0], AL[1], AL[2], AL[3], BH0, BH1);

// split one fp32 into bf16 hi + lo
__device__ __forceinline__ void split1(float v, __nv_bfloat16& h, __nv_bfloat16& l) {
    h = __float2bfloat16(v);
    l = __float2bfloat16(v - __bfloat162float(h));
}

// ---------------------------------------------------------------- GEMM1
// C[768,4096] = W[768,256] @ X[256,4096] per batch, bf16x3 tensor cores.
// Block 128(M)x64(N), kstep 16, 256 thr (8 warps: 4M x 2N; warp tile 32x32).
// fp32 global loads with register prefetch; split to bf16 planes at smem store.
#define G1_SA 24   // 16 k + 8 pad  (80B-class stride -> conflict-free ldsm)
#define G1_SB 72   // 64 n + 8 pad

__global__ __launch_bounds__(256) void k_gemm1(const float* __restrict__ x,
                                               const float* __restrict__ w) {
    __shared__ __nv_bfloat16 sAh[128 * G1_SA];
    __shared__ __nv_bfloat16 sAl[128 * G1_SA];
    __shared__ __nv_bfloat16 sBh[16 * G1_SB];
    __shared__ __nv_bfloat16 sBl[16 * G1_SB];

    const int tid = threadIdx.x, lane = tid & 31, wid = tid >> 5;
    const int wm = wid >> 1, wn = wid & 1;
    const int n0 = blockIdx.x * 64, m0 = blockIdx.y * 128, b = blockIdx.z;
    const float* X = x + (size_t)b * C_ * N_;

    // stage mapping
    const int arow = tid >> 1, akc = (tid & 1) * 8;       // A: 128 rows x 16 k
    const int brow = tid >> 4, bnc = (tid & 15) * 4;      // B: 16 k x 64 n

    float acc[2][4][4];
    #pragma unroll
    for (int i = 0; i < 2; ++i)
        #pragma unroll
        for (int j = 0; j < 4; ++j)
            #pragma unroll
            for (int e = 0; e < 4; ++e) acc[i][j][e] = 0.f;

    float4 aS0, aS1, bS0;
    aS0 = *reinterpret_cast<const float4*>(w + (size_t)(m0 + arow) * 256 + akc);
    aS1 = *reinterpret_cast<const float4*>(w + (size_t)(m0 + arow) * 256 + akc + 4);
    bS0 = *reinterpret_cast<const float4*>(X + (size_t)brow * N_ + n0 + bnc);

    #pragma unroll 1
    for (int t = 0; t < 16; ++t) {
        // store stage -> smem (split hi/lo)
        {
            int ao = arow * G1_SA + akc;
            __nv_bfloat16 h, l;
            split1(aS0.x, h, l); sAh[ao+0] = h; sAl[ao+0] = l;
            split1(aS0.y, h, l); sAh[ao+1] = h; sAl[ao+1] = l;
            split1(aS0.z, h, l); sAh[ao+2] = h; sAl[ao+2] = l;
            split1(aS0.w, h, l); sAh[ao+3] = h; sAl[ao+3] = l;
            split1(aS1.x, h, l); sAh[ao+4] = h; sAl[ao+4] = l;
            split1(aS1.y, h, l); sAh[ao+5] = h; sAl[ao+5] = l;
            split1(aS1.z, h, l); sAh[ao+6] = h; sAl[ao+6] = l;
            split1(aS1.w, h, l); sAh[ao+7] = h; sAl[ao+7] = l;
            int bo = brow * G1_SB + bnc;
            split1(bS0.x, h, l); sBh[bo+0] = h; sBl[bo+0] = l;
            split1(bS0.y, h, l); sBh[bo+1] = h; sBl[bo+1] = l;
            split1(bS0.z, h, l); sBh[bo+2] = h; sBl[bo+2] = l;
            split1(bS0.w, h, l); sBh[bo+3] = h; sBl[bo+3] = l;
        }
        __syncthreads();
        if (t < 15) {
            int kt = (t + 1) * 16;
            aS0 = *reinterpret_cast<const float4*>(w + (size_t)(m0 + arow) * 256 + kt + akc);
            aS1 = *reinterpret_cast<const float4*>(w + (size_t)(m0 + arow) * 256 + kt + akc + 4);
            bS0 = *reinterpret_cast<const float4*>(X + (size_t)(kt + brow) * N_ + n0 + bnc);
        }

        // compute one k16
        uint32_t ah[2][4], al[2][4];
        #pragma unroll
        for (int mf = 0; mf < 2; ++mf) {
            int rowm = wm*32 + mf*16 + (lane & 15);
            int colk = (lane >> 4) * 8;
            ldsm_x4(ah[mf][0], ah[mf][1], ah[mf][2], ah[mf][3],
                    smem_u32(sAh + rowm * G1_SA + colk));
            ldsm_x4(al[mf][0], al[mf][1], al[mf][2], al[mf][3],
                    smem_u32(sAl + rowm * G1_SA + colk));
        }
        uint32_t bh[2][4], bl[2][4];
        #pragma unroll
        for (int p = 0; p < 2; ++p) {
            int krow = lane & 15;
            int ncol = wn*32 + p*16 + (lane >> 4) * 8;
            ldsm_x4t(bh[p][0], bh[p][1], bh[p][2], bh[p][3],
                     smem_u32(sBh + krow * G1_SB + ncol));
            ldsm_x4t(bl[p][0], bl[p][1], bl[p][2], bl[p][3],
                     smem_u32(sBl + krow * G1_SB + ncol));
        }
        #pragma unroll
        for (int mf = 0; mf < 2; ++mf) {
            #pragma unroll
            for (int nf = 0; nf < 4; ++nf) {
                const int p = nf >> 1, hh = (nf & 1) * 2;
                MMA3(acc[mf][nf], ah[mf], al[mf],
                     bh[p][hh], bh[p][hh+1], bl[p][hh], bl[p][hh+1]);
            }
        }
        __syncthreads();
    }

    // epilogue: q -> elu+1, k -> elu+1, v raw; all fp32 stores
    const int type = m0 >> 8;  // 0=q, 1=k, 2=v  (m0 in {0,128,...,640})
    #pragma unroll
    for (int mf = 0; mf < 2; ++mf) {
        int rbase = m0 + wm*32 + mf*16 + (lane >> 2);
        #pragma unroll
        for (int nf = 0; nf < 4; ++nf) {
            int c = n0 + wn*32 + nf*8 + (lane & 3) * 2;
            #pragma unroll
            for (int rh = 0; rh < 2; ++rh) {
                int r = rbase + rh * 8;
                float v0 = acc[mf][nf][rh*2 + 0];
                float v1 = acc[mf][nf][rh*2 + 1];
                if (type == 0) {
                    *reinterpret_cast<float2*>(&g_QK[((size_t)b*C_ + r)*N_ + c]) =
                        make_float2(elu1(v0), elu1(v1));
                } else if (type == 1) {
                    *reinterpret_cast<float2*>(&g_KK[((size_t)b*C_ + (r-256))*N_ + c]) =
                        make_float2(elu1(v0), elu1(v1));
                } else {
                    *reinterpret_cast<float2*>(&g_V[((size_t)b*C_ + (r-512))*N_ + c]) =
                        make_float2(v0, v1);
                }
            }
        }
    }
}

// ---------------------------------------------------------------- reduce
__global__ __launch_bounds__(256) void k_reduce() {
    const int c = blockIdx.x, b = blockIdx.y;
    const float4* kk = reinterpret_cast<const float4*>(&g_KK[((size_t)b*C_ + c) * N_]);
    const float4* vv = reinterpret_cast<const float4*>(&g_V [((size_t)b*C_ + c) * N_]);
    float skv = 0.f, sk = 0.f;
    for (int i = threadIdx.x; i < 1024; i += 256) {
        float4 k4 = kk[i], v4 = vv[i];
        skv = fmaf(k4.x, v4.x, skv); skv = fmaf(k4.y, v4.y, skv);
        skv = fmaf(k4.z, v4.z, skv); skv = fmaf(k4.w, v4.w, skv);
        sk += k4.x + k4.y + k4.z + k4.w;
    }
    #pragma unroll
    for (int o = 16; o > 0; o >>= 1) {
        skv += __shfl_xor_sync(0xFFFFFFFFu, skv, o);
        sk  += __shfl_xor_sync(0xFFFFFFFFu, sk, o);
    }
    __shared__ float s1[8], s2[8];
    int w = threadIdx.x >> 5, l = threadIdx.x & 31;
    if (l == 0) { s1[w] = skv; s2[w] = sk; }
    __syncthreads();
    if (threadIdx.x == 0) {
        float a = 0.f, d = 0.f;
        #pragma unroll
        for (int i = 0; i < 8; ++i) { a += s1[i]; d += s2[i]; }
        g_s[b * C_ + c] = a / fmaxf(d, 1e-6f);
    }
}

// ---------------------------------------------------------------- GEMM2 + LN
// out[256,4096] = (W_out * s_col)[256,256] @ QK[256,4096] per batch, fused LN.
// Block 256(M)x32(N), kstep 16, 256 thr (4M x 2N warps; warp tile 64x16).
// s folded into A at staging; fp32 loads, on-the-fly split.
#define G2_SA 24
#define G2_SB 40

__global__ __launch_bounds__(256) void k_gemm2(const float* __restrict__ w_out,
                                               const float* __restrict__ gamma,
                                               const float* __restrict__ beta,
                                               float* __restrict__ out) {
    __shared__ __nv_bfloat16 sAh[256 * G2_SA];
    __shared__ __nv_bfloat16 sAl[256 * G2_SA];
    __shared__ __nv_bfloat16 sBh[16 * G2_SB];
    __shared__ __nv_bfloat16 sBl[16 * G2_SB];
    __shared__ float s_sm[256], g_sm[256], be_sm[256];
    __shared__ float red_s[32][32];
    __shared__ float red_q[32][32];
    __shared__ float mu_s[32], rs_s[32];

    const int tid = threadIdx.x, lane = tid & 31, wid = tid >> 5;
    const int wm = wid >> 1, wn = wid & 1;
    const int n0 = blockIdx.x * 32, b = blockIdx.y;
    const float* QK = g_QK + (size_t)b * C_ * N_;

    s_sm[tid]  = g_s[b * C_ + tid];
    g_sm[tid]  = gamma[tid];
    be_sm[tid] = beta[tid];
    __syncthreads();

    // stage mapping: A row = tid (one row/thread, 16 k); B 16 k x 32 n, float2
    const int brow = tid >> 4, bnc = (tid & 15) * 2;

    float acc[4][2][4];
    #pragma unroll
    for (int i = 0; i < 4; ++i)
        #pragma unroll
        for (int j = 0; j < 2; ++j)
            #pragma unroll
            for (int e = 0; e < 4; ++e) acc[i][j][e] = 0.f;

    float4 aS0, aS1, aS2, aS3;
    float2 bS0;
    {
        const float* wr = w_out + (size_t)tid * 256;
        aS0 = *reinterpret_cast<const float4*>(wr + 0);
        aS1 = *reinterpret_cast<const float4*>(wr + 4);
        aS2 = *reinterpret_cast<const float4*>(wr + 8);
        aS3 = *reinterpret_cast<const float4*>(wr + 12);
        bS0 = *reinterpret_cast<const float2*>(QK + (size_t)brow * N_ + n0 + bnc);
    }

    #pragma unroll 1
    for (int t = 0; t < 16; ++t) {
        const int kt = t * 16;
        // store stage -> smem (A scaled by s, split)
        {
            int ao = tid * G2_SA;
            __nv_bfloat16 h, l;
            split1(aS0.x * s_sm[kt+ 0], h, l); sAh[ao+ 0] = h; sAl[ao+ 0] = l;
            split1(aS0.y * s_sm[kt+ 1], h, l); sAh[ao+ 1] = h; sAl[ao+ 1] = l;
            split1(aS0.z * s_sm[kt+ 2], h, l); sAh[ao+ 2] = h; sAl[ao+ 2] = l;
            split1(aS0.w * s_sm[kt+ 3], h, l); sAh[ao+ 3] = h; sAl[ao+ 3] = l;
            split1(aS1.x * s_sm[kt+ 4], h, l); sAh[ao+ 4] = h; sAl[ao+ 4] = l;
            split1(aS1.y * s_sm[kt+ 5], h, l); sAh[ao+ 5] = h; sAl[ao+ 5] = l;
            split1(aS1.z * s_sm[kt+ 6], h, l); sAh[ao+ 6] = h; sAl[ao+ 6] = l;
            split1(aS1.w * s_sm[kt+ 7], h, l); sAh[ao+ 7] = h; sAl[ao+ 7] = l;
            split1(aS2.x * s_sm[kt+ 8], h, l); sAh[ao+ 8] = h; sAl[ao+ 8] = l;
            split1(aS2.y * s_sm[kt+ 9], h, l); sAh[ao+ 9] = h; sAl[ao+ 9] = l;
            split1(aS2.z * s_sm[kt+10], h, l); sAh[ao+10] = h; sAl[ao+10] = l;
            split1(aS2.w * s_sm[kt+11], h, l); sAh[ao+11] = h; sAl[ao+11] = l;
            split1(aS3.x * s_sm[kt+12], h, l); sAh[ao+12] = h; sAl[ao+12] = l;
            split1(aS3.y * s_sm[kt+13], h, l); sAh[ao+13] = h; sAl[ao+13] = l;
            split1(aS3.z * s_sm[kt+14], h, l); sAh[ao+14] = h; sAl[ao+14] = l;
            split1(aS3.w * s_sm[kt+15], h, l); sAh[ao+15] = h; sAl[ao+15] = l;
            int bo = brow * G2_SB + bnc;
            split1(bS0.x, h, l); sBh[bo+0] = h; sBl[bo+0] = l;
            split1(bS0.y, h, l); sBh[bo+1] = h; sBl[bo+1] = l;
        }
        __syncthreads();
        if (t < 15) {
            int ktn = kt + 16;
            const float* wr = w_out + (size_t)tid * 256 + ktn;
            aS0 = *reinterpret_cast<const float4*>(wr + 0);
            aS1 = *reinterpret_cast<const float4*>(wr + 4);
            aS2 = *reinterpret_cast<const float4*>(wr + 8);
            aS3 = *reinterpret_cast<const float4*>(wr + 12);
            bS0 = *reinterpret_cast<const float2*>(QK + (size_t)(ktn + brow) * N_ + n0 + bnc);
        }

        // compute one k16
        uint32_t ah[4][4], al[4][4];
        #pragma unroll
        for (int mf = 0; mf < 4; ++mf) {
            int rowm = wm*64 + mf*16 + (lane & 15);
            int colk = (lane >> 4) * 8;
            ldsm_x4(ah[mf][0], ah[mf][1], ah[mf][2], ah[mf][3],
                    smem_u32(sAh + rowm * G2_SA + colk));
            ldsm_x4(al[mf][0], al[mf][1], al[mf][2], al[mf][3],
                    smem_u32(sAl + rowm * G2_SA + colk));
        }
        uint32_t bh[4], bl[4];
        {
            int krow = lane & 15;
            int ncol = wn*16 + (lane >> 4) * 8;
            ldsm_x4t(bh[0], bh[1], bh[2], bh[3],
                     smem_u32(sBh + krow * G2_SB + ncol));
            ldsm_x4t(bl[0], bl[1], bl[2], bl[3],
                     smem_u32(sBl + krow * G2_SB + ncol));
        }
        #pragma unroll
        for (int mf = 0; mf < 4; ++mf) {
            #pragma unroll
            for (int nf = 0; nf < 2; ++nf) {
                const int hh = nf * 2;
                MMA3(acc[mf][nf], ah[mf], al[mf],
                     bh[hh], bh[hh+1], bl[hh], bl[hh+1]);
            }
        }
        __syncthreads();
    }

    // ---- fused LayerNorm over the 256 channels this block owns ----
    #pragma unroll
    for (int nf = 0; nf < 2; ++nf)
        #pragma unroll
        for (int e = 0; e < 2; ++e) {
            float s = 0.f, q = 0.f;
            #pragma unroll
            for (int mf = 0; mf < 4; ++mf)
                #pragma unroll
                for (int rh = 0; rh < 2; ++rh) {
                    float v = acc[mf][nf][rh*2 + e];
                    s += v; q = fmaf(v, v, q);
                }
            int col = wn*16 + nf*8 + (lane & 3)*2 + e;
            red_s[wm*8 + (lane >> 2)][col] = s;
            red_q[wm*8 + (lane >> 2)][col] = q;
        }
    __syncthreads();
    if (tid < 32) {
        float s = 0.f, q = 0.f;
        #pragma unroll
        for (int r = 0; r < 32; ++r) { s += red_s[r][tid]; q += red_q[r][tid]; }
        float mu  = s * (1.f / 256.f);
        float var = q * (1.f / 256.f) - mu * mu;
        mu_s[tid] = mu;
        rs_s[tid] = rsqrtf(var + 1e-5f);
    }
    __syncthreads();

    #pragma unroll
    for (int mf = 0; mf < 4; ++mf) {
        int rbase = wm*64 + mf*16 + (lane >> 2);
        #pragma unroll
        for (int nf = 0; nf < 2; ++nf) {
            int col = wn*16 + nf*8 + (lane & 3)*2;
            #pragma unroll
            for (int rh = 0; rh < 2; ++rh) {
                int r = rbase + rh*8;
                float ga = g_sm[r], be = be_sm[r];
                float v0 = (acc[mf][nf][rh*2+0] - mu_s[col])   * rs_s[col]   * ga + be;
                float v1 = (acc[mf][nf][rh*2+1] - mu_s[col+1]) * rs_s[col+1] * ga + be;
                *reinterpret_cast<float2*>(&out[((size_t)b*C_ + r)*N_ + n0 + col]) =
                    make_float2(v0, v1);
            }
        }
    }
}

// ----------------------------------------------------------------
extern "C" void kernel_launch(void* const* d_in, const int* in_sizes, int n_in,
                              void* d_out, int out_size) {
    const float* x     = (const float*)d_in[0];
    const float* w_qkv = (const float*)d_in[1];
    const float* w_out = (const float*)d_in[2];
    const float* gamma = (const float*)d_in[3];
    const float* beta  = (const float*)d_in[4];
    float* out = (float*)d_out;

    k_gemm1 <<<dim3(64, 6, 16), 256>>>(x, w_qkv);
    k_reduce<<<dim3(256, 16),   256>>>();
    k_gemm2 <<<dim3(128, 16),   256>>>(w_out, gamma, beta, out);
}

// round 7
// speedup vs baseline: 1.2616x; 1.1949x over previous
#include <cuda_runtime.h>
#include <cuda_bf16.h>
#include <math.h>
#include <stdint.h>

// Shapes: x [16,256,4096], w_qkv [768,256], w_out [256,256], gamma/beta [256]
#define C_ 256
#define N_ 4096

// scratch: 3 x 64MiB fp32 planes (identical footprint to passing rounds 1/5)
__device__ float g_QK[16777216];   // elu(q)+1
__device__ float g_KK[16777216];   // elu(k)+1
__device__ float g_V [16777216];   // v
__device__ float g_s [4096];       // per (b,c) scale

// ---------------------------------------------------------------- helpers
__device__ __forceinline__ uint32_t smem_u32(const void* p) {
    return (uint32_t)__cvta_generic_to_shared(p);
}
__device__ __forceinline__ void ldsm_x4(uint32_t& r0, uint32_t& r1, uint32_t& r2, uint32_t& r3, uint32_t a) {
    asm volatile("ldmatrix.sync.aligned.m8n8.x4.shared.b16 {%0,%1,%2,%3}, [%4];"
                 : "=r"(r0), "=r"(r1), "=r"(r2), "=r"(r3) : "r"(a));
}
__device__ __forceinline__ void ldsm_x4t(uint32_t& r0, uint32_t& r1, uint32_t& r2, uint32_t& r3, uint32_t a) {
    asm volatile("ldmatrix.sync.aligned.m8n8.x4.trans.shared.b16 {%0,%1,%2,%3}, [%4];"
                 : "=r"(r0), "=r"(r1), "=r"(r2), "=r"(r3) : "r"(a));
}
__device__ __forceinline__ void mma_bf16(float& d0, float& d1, float& d2, float& d3,
                                         uint32_t a0, uint32_t a1, uint32_t a2, uint32_t a3,
                                         uint32_t b0, uint32_t b1) {
    asm volatile("mma.sync.aligned.m16n8k16.row.col.f32.bf16.bf16.f32 "
                 "{%0,%1,%2,%3},{%4,%5,%6,%7},{%8,%9},{%0,%1,%2,%3};"
                 : "+f"(d0), "+f"(d1), "+f"(d2), "+f"(d3)
                 : "r"(a0), "r"(a1), "r"(a2), "r"(a3), "r"(b0), "r"(b1));
}
__device__ __forceinline__ float elu1(float v) { return v > 0.f ? v + 1.f : expf(v); }

// 3-split mma: d += ah*bh + ah*bl + al*bh
#define MMA3(ACC, AH, AL, BH0, BH1, BL0, BL1)                                   \
    mma_bf16(ACC[0], ACC[1], ACC[2], ACC[3],                                    \
             AH[0], AH[1], AH[2], AH[3], BH0, BH1);                             \
    mma_bf16(ACC[0], ACC[1], ACC[2], ACC[3],                                    \
             AH[0], AH[1], AH[2], AH[3], BL0, BL1);                             \
    mma_bf16(ACC[0], ACC[1], ACC[2], ACC[3],                                    \
             AL[0], AL[1], AL[2], AL[3], BH0, BH1);

// split (a,b) fp32 pair -> packed bf16x2 hi (return) and lo (out-param).
// Pure scalar integer ops: no unions, no address-taken locals.
__device__ __forceinline__ uint32_t packsplit(float a, float b, uint32_t& lo) {
    __nv_bfloat16 ha = __float2bfloat16(a);
    __nv_bfloat16 hb = __float2bfloat16(b);
    float ra = a - __bfloat162float(ha);
    float rb = b - __bfloat162float(hb);
    lo = (uint32_t)__bfloat16_as_ushort(__float2bfloat16(ra))
       | ((uint32_t)__bfloat16_as_ushort(__float2bfloat16(rb)) << 16);
    return (uint32_t)__bfloat16_as_ushort(ha)
         | ((uint32_t)__bfloat16_as_ushort(hb) << 16);
}

// ---------------------------------------------------------------- GEMM1
// C[768,4096] = W[768,256] @ X[256,4096] per batch, bf16x3 tensor cores.
// Block 128(M)x64(N), kstep 32, 256 thr (8 warps: 4M x 2N; warp tile 32x32).
// fp32 LDG + integer-packed 128-bit STS; reg-prefetch double buffering.
#define G1_SA 40   // 32 k + 8 pad  (80B row stride)
#define G1_SB 72   // 64 n + 8 pad  (144B row stride)

__global__ __launch_bounds__(256) void k_gemm1(const float* __restrict__ x,
                                               const float* __restrict__ w) {
    __shared__ __nv_bfloat16 sAh[128 * G1_SA];
    __shared__ __nv_bfloat16 sAl[128 * G1_SA];
    __shared__ __nv_bfloat16 sBh[32 * G1_SB];
    __shared__ __nv_bfloat16 sBl[32 * G1_SB];

    const int tid = threadIdx.x, lane = tid & 31, wid = tid >> 5;
    const int wm = wid >> 1, wn = wid & 1;
    const int n0 = blockIdx.x * 64, m0 = blockIdx.y * 128, b = blockIdx.z;
    const float* X = x + (size_t)b * C_ * N_;

    // A stage: 128 rows x 32 k; thread -> (row = tid&127, kc = (tid>>7)*16)
    const int arow = tid & 127, akc = (tid >> 7) * 16;
    // B stage: 32 rows x 64 n; thread -> (row = tid>>3, nc = (tid&7)*8)
    const int brow = tid >> 3, bnc = (tid & 7) * 8;

    float acc[2][4][4];
    #pragma unroll
    for (int i = 0; i < 2; ++i)
        #pragma unroll
        for (int j = 0; j < 4; ++j)
            #pragma unroll
            for (int e = 0; e < 4; ++e) acc[i][j][e] = 0.f;

    float4 a0, a1, a2, a3, b0, b1;
    {
        const float* wp = w + (size_t)(m0 + arow) * 256 + akc;
        a0 = *reinterpret_cast<const float4*>(wp + 0);
        a1 = *reinterpret_cast<const float4*>(wp + 4);
        a2 = *reinterpret_cast<const float4*>(wp + 8);
        a3 = *reinterpret_cast<const float4*>(wp + 12);
        const float* xp = X + (size_t)brow * N_ + n0 + bnc;
        b0 = *reinterpret_cast<const float4*>(xp + 0);
        b1 = *reinterpret_cast<const float4*>(xp + 4);
    }

    #pragma unroll 1
    for (int t = 0; t < 8; ++t) {
        // pack stage -> smem (128-bit stores only)
        {
            uint32_t l0, l1, l2, l3, l4, l5, l6, l7;
            uint32_t h0 = packsplit(a0.x, a0.y, l0);
            uint32_t h1 = packsplit(a0.z, a0.w, l1);
            uint32_t h2 = packsplit(a1.x, a1.y, l2);
            uint32_t h3 = packsplit(a1.z, a1.w, l3);
            uint32_t h4 = packsplit(a2.x, a2.y, l4);
            uint32_t h5 = packsplit(a2.z, a2.w, l5);
            uint32_t h6 = packsplit(a3.x, a3.y, l6);
            uint32_t h7 = packsplit(a3.z, a3.w, l7);
            const int ao = arow * G1_SA + akc;
            *reinterpret_cast<uint4*>(&sAh[ao])     = make_uint4(h0, h1, h2, h3);
            *reinterpret_cast<uint4*>(&sAh[ao + 8]) = make_uint4(h4, h5, h6, h7);
            *reinterpret_cast<uint4*>(&sAl[ao])     = make_uint4(l0, l1, l2, l3);
            *reinterpret_cast<uint4*>(&sAl[ao + 8]) = make_uint4(l4, l5, l6, l7);
            uint32_t m0_, m1_, m2_, m3_;
            uint32_t g0 = packsplit(b0.x, b0.y, m0_);
            uint32_t g1 = packsplit(b0.z, b0.w, m1_);
            uint32_t g2 = packsplit(b1.x, b1.y, m2_);
            uint32_t g3 = packsplit(b1.z, b1.w, m3_);
            const int bo = brow * G1_SB + bnc;
            *reinterpret_cast<uint4*>(&sBh[bo]) = make_uint4(g0, g1, g2, g3);
            *reinterpret_cast<uint4*>(&sBl[bo]) = make_uint4(m0_, m1_, m2_, m3_);
        }
        __syncthreads();
        if (t < 7) {
            int kt = (t + 1) * 32;
            const float* wp = w + (size_t)(m0 + arow) * 256 + kt + akc;
            a0 = *reinterpret_cast<const float4*>(wp + 0);
            a1 = *reinterpret_cast<const float4*>(wp + 4);
            a2 = *reinterpret_cast<const float4*>(wp + 8);
            a3 = *reinterpret_cast<const float4*>(wp + 12);
            const float* xp = X + (size_t)(kt + brow) * N_ + n0 + bnc;
            b0 = *reinterpret_cast<const float4*>(xp + 0);
            b1 = *reinterpret_cast<const float4*>(xp + 4);
        }

        #pragma unroll
        for (int k2 = 0; k2 < 2; ++k2) {
            const int k16 = k2 * 16;
            uint32_t ah[2][4], al[2][4];
            #pragma unroll
            for (int mf = 0; mf < 2; ++mf) {
                int rowm = wm*32 + mf*16 + (lane & 15);
                int colk = k16 + (lane >> 4) * 8;
                ldsm_x4(ah[mf][0], ah[mf][1], ah[mf][2], ah[mf][3],
                        smem_u32(sAh + rowm * G1_SA + colk));
                ldsm_x4(al[mf][0], al[mf][1], al[mf][2], al[mf][3],
                        smem_u32(sAl + rowm * G1_SA + colk));
            }
            uint32_t bh[2][4], bl[2][4];
            #pragma unroll
            for (int p = 0; p < 2; ++p) {
                int krow = k16 + (lane & 15);
                int ncol = wn*32 + p*16 + (lane >> 4) * 8;
                ldsm_x4t(bh[p][0], bh[p][1], bh[p][2], bh[p][3],
                         smem_u32(sBh + krow * G1_SB + ncol));
                ldsm_x4t(bl[p][0], bl[p][1], bl[p][2], bl[p][3],
                         smem_u32(sBl + krow * G1_SB + ncol));
            }
            #pragma unroll
            for (int mf = 0; mf < 2; ++mf) {
                #pragma unroll
                for (int nf = 0; nf < 4; ++nf) {
                    const int p = nf >> 1, hh = (nf & 1) * 2;
                    MMA3(acc[mf][nf], ah[mf], al[mf],
                         bh[p][hh], bh[p][hh+1], bl[p][hh], bl[p][hh+1]);
                }
            }
        }
        __syncthreads();
    }

    // epilogue: q,k -> elu+1; v raw; fp32 stores
    const int type = m0 >> 8;  // 0=q, 1=k, 2=v
    #pragma unroll
    for (int mf = 0; mf < 2; ++mf) {
        int rbase = m0 + wm*32 + mf*16 + (lane >> 2);
        #pragma unroll
        for (int nf = 0; nf < 4; ++nf) {
            int c = n0 + wn*32 + nf*8 + (lane & 3) * 2;
            #pragma unroll
            for (int rh = 0; rh < 2; ++rh) {
                int r = rbase + rh * 8;
                float v0 = acc[mf][nf][rh*2 + 0];
                float v1 = acc[mf][nf][rh*2 + 1];
                if (type == 0) {
                    *reinterpret_cast<float2*>(&g_QK[((size_t)b*C_ + r)*N_ + c]) =
                        make_float2(elu1(v0), elu1(v1));
                } else if (type == 1) {
                    *reinterpret_cast<float2*>(&g_KK[((size_t)b*C_ + (r-256))*N_ + c]) =
                        make_float2(elu1(v0), elu1(v1));
                } else {
                    *reinterpret_cast<float2*>(&g_V[((size_t)b*C_ + (r-512))*N_ + c]) =
                        make_float2(v0, v1);
                }
            }
        }
    }
}

// ---------------------------------------------------------------- reduce (verbatim round 5)
__global__ __launch_bounds__(256) void k_reduce() {
    const int c = blockIdx.x, b = blockIdx.y;
    const float4* kk = reinterpret_cast<const float4*>(&g_KK[((size_t)b*C_ + c) * N_]);
    const float4* vv = reinterpret_cast<const float4*>(&g_V [((size_t)b*C_ + c) * N_]);
    float skv = 0.f, sk = 0.f;
    for (int i = threadIdx.x; i < 1024; i += 256) {
        float4 k4 = kk[i], v4 = vv[i];
        skv = fmaf(k4.x, v4.x, skv); skv = fmaf(k4.y, v4.y, skv);
        skv = fmaf(k4.z, v4.z, skv); skv = fmaf(k4.w, v4.w, skv);
        sk += k4.x + k4.y + k4.z + k4.w;
    }
    #pragma unroll
    for (int o = 16; o > 0; o >>= 1) {
        skv += __shfl_xor_sync(0xFFFFFFFFu, skv, o);
        sk  += __shfl_xor_sync(0xFFFFFFFFu, sk, o);
    }
    __shared__ float s1[8], s2[8];
    int w = threadIdx.x >> 5, l = threadIdx.x & 31;
    if (l == 0) { s1[w] = skv; s2[w] = sk; }
    __syncthreads();
    if (threadIdx.x == 0) {
        float a = 0.f, d = 0.f;
        #pragma unroll
        for (int i = 0; i < 8; ++i) { a += s1[i]; d += s2[i]; }
        g_s[b * C_ + c] = a / fmaxf(d, 1e-6f);
    }
}

// ---------------------------------------------------------------- GEMM2 + LN
// out[256,4096] = W_out[256,256] @ (s_row * QK)[256,4096] per batch, fused LN.
// s folded into B rows (1 broadcast LDS per thread/iter).
// Block 256(M)x32(N), kstep 16, 256 thr (4M x 2N warps; warp tile 64x16).
#define G2_SA 24
#define G2_SB 40

__global__ __launch_bounds__(256) void k_gemm2(const float* __restrict__ w_out,
                                               const float* __restrict__ gamma,
                                               const float* __restrict__ beta,
                                               float* __restrict__ out) {
    __shared__ __nv_bfloat16 sAh[256 * G2_SA];
    __shared__ __nv_bfloat16 sAl[256 * G2_SA];
    __shared__ __nv_bfloat16 sBh[16 * G2_SB];
    __shared__ __nv_bfloat16 sBl[16 * G2_SB];
    __shared__ float s_sm[256], g_sm[256], be_sm[256];
    __shared__ float red_s[32][32];
    __shared__ float red_q[32][32];
    __shared__ float mu_s[32], rs_s[32];

    const int tid = threadIdx.x, lane = tid & 31, wid = tid >> 5;
    const int wm = wid >> 1, wn = wid & 1;
    const int n0 = blockIdx.x * 32, b = blockIdx.y;
    const float* QK = g_QK + (size_t)b * C_ * N_;

    s_sm[tid]  = g_s[b * C_ + tid];
    g_sm[tid]  = gamma[tid];
    be_sm[tid] = beta[tid];
    __syncthreads();

    // A stage: 256 rows x 16 k; thread -> row tid, 16 consecutive k
    // B stage: 16 rows x 32 n; tid<64 -> (row = tid>>2, nc = (tid&3)*8), both planes
    const int brow = (tid & 63) >> 2, bnc = (tid & 3) * 8;

    float acc[4][2][4];
    #pragma unroll
    for (int i = 0; i < 4; ++i)
        #pragma unroll
        for (int j = 0; j < 2; ++j)
            #pragma unroll
            for (int e = 0; e < 4; ++e) acc[i][j][e] = 0.f;

    float4 a0, a1, a2, a3, b0, b1;
    {
        const float* wp = w_out + (size_t)tid * 256;
        a0 = *reinterpret_cast<const float4*>(wp + 0);
        a1 = *reinterpret_cast<const float4*>(wp + 4);
        a2 = *reinterpret_cast<const float4*>(wp + 8);
        a3 = *reinterpret_cast<const float4*>(wp + 12);
        if (tid < 64) {
            const float* qp = QK + (size_t)brow * N_ + n0 + bnc;
            b0 = *reinterpret_cast<const float4*>(qp + 0);
            b1 = *reinterpret_cast<const float4*>(qp + 4);
        }
    }

    #pragma unroll 1
    for (int t = 0; t < 16; ++t) {
        const int kt = t * 16;
        {
            uint32_t l0, l1, l2, l3, l4, l5, l6, l7;
            uint32_t h0 = packsplit(a0.x, a0.y, l0);
            uint32_t h1 = packsplit(a0.z, a0.w, l1);
            uint32_t h2 = packsplit(a1.x, a1.y, l2);
            uint32_t h3 = packsplit(a1.z, a1.w, l3);
            uint32_t h4 = packsplit(a2.x, a2.y, l4);
            uint32_t h5 = packsplit(a2.z, a2.w, l5);
            uint32_t h6 = packsplit(a3.x, a3.y, l6);
            uint32_t h7 = packsplit(a3.z, a3.w, l7);
            const int ao = tid * G2_SA;
            *reinterpret_cast<uint4*>(&sAh[ao])     = make_uint4(h0, h1, h2, h3);
            *reinterpret_cast<uint4*>(&sAh[ao + 8]) = make_uint4(h4, h5, h6, h7);
            *reinterpret_cast<uint4*>(&sAl[ao])     = make_uint4(l0, l1, l2, l3);
            *reinterpret_cast<uint4*>(&sAl[ao + 8]) = make_uint4(l4, l5, l6, l7);
            if (tid < 64) {
                float sv = s_sm[kt + brow];
                uint32_t m0_, m1_, m2_, m3_;
                uint32_t g0 = packsplit(b0.x * sv, b0.y * sv, m0_);
                uint32_t g1 = packsplit(b0.z * sv, b0.w * sv, m1_);
                uint32_t g2 = packsplit(b1.x * sv, b1.y * sv, m2_);
                uint32_t g3 = packsplit(b1.z * sv, b1.w * sv, m3_);
                const int bo = brow * G2_SB + bnc;
                *reinterpret_cast<uint4*>(&sBh[bo]) = make_uint4(g0, g1, g2, g3);
                *reinterpret_cast<uint4*>(&sBl[bo]) = make_uint4(m0_, m1_, m2_, m3_);
            }
        }
        __syncthreads();
        if (t < 15) {
            int ktn = kt + 16;
            const float* wp = w_out + (size_t)tid * 256 + ktn;
            a0 = *reinterpret_cast<const float4*>(wp + 0);
            a1 = *reinterpret_cast<const float4*>(wp + 4);
            a2 = *reinterpret_cast<const float4*>(wp + 8);
            a3 = *reinterpret_cast<const float4*>(wp + 12);
            if (tid < 64) {
                const float* qp = QK + (size_t)(ktn + brow) * N_ + n0 + bnc;
                b0 = *reinterpret_cast<const float4*>(qp + 0);
                b1 = *reinterpret_cast<const float4*>(qp + 4);
            }
        }

        uint32_t ah[4][4], al[4][4];
        #pragma unroll
        for (int mf = 0; mf < 4; ++mf) {
            int rowm = wm*64 + mf*16 + (lane & 15);
            int colk = (lane >> 4) * 8;
            ldsm_x4(ah[mf][0], ah[mf][1], ah[mf][2], ah[mf][3],
                    smem_u32(sAh + rowm * G2_SA + colk));
            ldsm_x4(al[mf][0], al[mf][1], al[mf][2], al[mf][3],
                    smem_u32(sAl + rowm * G2_SA + colk));
        }
        uint32_t bh[4], bl[4];
        {
            int krow = lane & 15;
            int ncol = wn*16 + (lane >> 4) * 8;
            ldsm_x4t(bh[0], bh[1], bh[2], bh[3],
                     smem_u32(sBh + krow * G2_SB + ncol));
            ldsm_x4t(bl[0], bl[1], bl[2], bl[3],
                     smem_u32(sBl + krow * G2_SB + ncol));
        }
        #pragma unroll
        for (int mf = 0; mf < 4; ++mf) {
            #pragma unroll
            for (int nf = 0; nf < 2; ++nf) {
                const int hh = nf * 2;
                MMA3(acc[mf][nf], ah[mf], al[mf],
                     bh[hh], bh[hh+1], bl[hh], bl[hh+1]);
            }
        }
        __syncthreads();
    }

    // ---- fused LayerNorm over the 256 channels this block owns ----
    #pragma unroll
    for (int nf = 0; nf < 2; ++nf)
        #pragma unroll
        for (int e = 0; e < 2; ++e) {
            float s = 0.f, q = 0.f;
            #pragma unroll
            for (int mf = 0; mf < 4; ++mf)
                #pragma unroll
                for (int rh = 0; rh < 2; ++rh) {
                    float v = acc[mf][nf][rh*2 + e];
                    s += v; q = fmaf(v, v, q);
                }
            int col = wn*16 + nf*8 + (lane & 3)*2 + e;
            red_s[wm*8 + (lane >> 2)][col] = s;
            red_q[wm*8 + (lane >> 2)][col] = q;
        }
    __syncthreads();
    if (tid < 32) {
        float s = 0.f, q = 0.f;
        #pragma unroll
        for (int r = 0; r < 32; ++r) { s += red_s[r][tid]; q += red_q[r][tid]; }
        float mu  = s * (1.f / 256.f);
        float var = q * (1.f / 256.f) - mu * mu;
        mu_s[tid] = mu;
        rs_s[tid] = rsqrtf(var + 1e-5f);
    }
    __syncthreads();

    #pragma unroll
    for (int mf = 0; mf < 4; ++mf) {
        int rbase = wm*64 + mf*16 + (lane >> 2);
        #pragma unroll
        for (int nf = 0; nf < 2; ++nf) {
            int col = wn*16 + nf*8 + (lane & 3)*2;
            #pragma unroll
            for (int rh = 0; rh < 2; ++rh) {
                int r = rbase + rh*8;
                float ga = g_sm[r], be = be_sm[r];
                float v0 = (acc[mf][nf][rh*2+0] - mu_s[col])   * rs_s[col]   * ga + be;
                float v1 = (acc[mf][nf][rh*2+1] - mu_s[col+1]) * rs_s[col+1] * ga + be;
                *reinterpret_cast<float2*>(&out[((size_t)b*C_ + r)*N_ + n0 + col]) =
                    make_float2(v0, v1);
            }
        }
    }
}

// ----------------------------------------------------------------
extern "C" void kernel_launch(void* const* d_in, const int* in_sizes, int n_in,
                              void* d_out, int out_size) {
    const float* x     = (const float*)d_in[0];
    const float* w_qkv = (const float*)d_in[1];
    const float* w_out = (const float*)d_in[2];
    const float* gamma = (const float*)d_in[3];
    const float* beta  = (const float*)d_in[4];
    float* out = (float*)d_out;

    k_gemm1 <<<dim3(64, 6, 16), 256>>>(x, w_qkv);
    k_reduce<<<dim3(256, 16),   256>>>();
    k_gemm2 <<<dim3(128, 16),   256>>>(w_out, gamma, beta, out);
}

// round 9
// speedup vs baseline: 1.5666x; 1.2418x over previous
#include <cuda_runtime.h>
#include <cuda_fp16.h>
#include <math.h>
#include <stdint.h>

// Shapes: x [16,256,4096], w_qkv [768,256], w_out [256,256], gamma/beta [256]
#define C_ 256
#define N_ 4096

// scratch: 3 x 64MiB fp32 planes (identical footprint to passing rounds 1/5/7)
__device__ float g_QK[16777216];   // elu(q)+1
__device__ float g_KK[16777216];   // elu(k)+1
__device__ float g_V [16777216];   // v
__device__ float g_s [4096];       // per (b,c) scale

// ---------------------------------------------------------------- helpers
__device__ __forceinline__ uint32_t smem_u32(const void* p) {
    return (uint32_t)__cvta_generic_to_shared(p);
}
__device__ __forceinline__ void ldsm_x4(uint32_t& r0, uint32_t& r1, uint32_t& r2, uint32_t& r3, uint32_t a) {
    asm volatile("ldmatrix.sync.aligned.m8n8.x4.shared.b16 {%0,%1,%2,%3}, [%4];"
                 : "=r"(r0), "=r"(r1), "=r"(r2), "=r"(r3) : "r"(a));
}
__device__ __forceinline__ void ldsm_x4t(uint32_t& r0, uint32_t& r1, uint32_t& r2, uint32_t& r3, uint32_t a) {
    asm volatile("ldmatrix.sync.aligned.m8n8.x4.trans.shared.b16 {%0,%1,%2,%3}, [%4];"
                 : "=r"(r0), "=r"(r1), "=r"(r2), "=r"(r3) : "r"(a));
}
__device__ __forceinline__ void mma_f16(float& d0, float& d1, float& d2, float& d3,
                                        uint32_t a0, uint32_t a1, uint32_t a2, uint32_t a3,
                                        uint32_t b0, uint32_t b1) {
    asm volatile("mma.sync.aligned.m16n8k16.row.col.f32.f16.f16.f32 "
                 "{%0,%1,%2,%3},{%4,%5,%6,%7},{%8,%9},{%0,%1,%2,%3};"
                 : "+f"(d0), "+f"(d1), "+f"(d2), "+f"(d3)
                 : "r"(a0), "r"(a1), "r"(a2), "r"(a3), "r"(b0), "r"(b1));
}
__device__ __forceinline__ float elu1(float v) { return v > 0.f ? v + 1.f : expf(v); }

// pack two fp32 -> fp16x2 (scalar integer ops only; no unions, no address-of)
__device__ __forceinline__ uint32_t packh(float a, float b) {
    return (uint32_t)__half_as_ushort(__float2half_rn(a))
         | ((uint32_t)__half_as_ushort(__float2half_rn(b)) << 16);
}

// ---------------------------------------------------------------- GEMM1
// C[768,4096] = W[768,256] @ X[256,4096] per batch, fp16 tensor cores.
// Block 128(M)x64(N), kstep 32, 256 thr (8 warps: 4M x 2N; warp tile 32x32).
#define G1_SA 40   // 32 k + 8 pad  (80B row stride)
#define G1_SB 72   // 64 n + 8 pad  (144B row stride)

__global__ __launch_bounds__(256) void k_gemm1(const float* __restrict__ x,
                                               const float* __restrict__ w) {
    __shared__ __half sA[128 * G1_SA];
    __shared__ __half sB[32 * G1_SB];

    const int tid = threadIdx.x, lane = tid & 31, wid = tid >> 5;
    const int wm = wid >> 1, wn = wid & 1;
    const int n0 = blockIdx.x * 64, m0 = blockIdx.y * 128, b = blockIdx.z;
    const float* X = x + (size_t)b * C_ * N_;

    // A stage: 128 rows x 32 k; thread -> (row = tid&127, kc = (tid>>7)*16)
    const int arow = tid & 127, akc = (tid >> 7) * 16;
    // B stage: 32 rows x 64 n; thread -> (row = tid>>3, nc = (tid&7)*8)
    const int brow = tid >> 3, bnc = (tid & 7) * 8;

    float acc[2][4][4];
    #pragma unroll
    for (int i = 0; i < 2; ++i)
        #pragma unroll
        for (int j = 0; j < 4; ++j)
            #pragma unroll
            for (int e = 0; e < 4; ++e) acc[i][j][e] = 0.f;

    float4 a0, a1, a2, a3, b0, b1;
    {
        const float* wp = w + (size_t)(m0 + arow) * 256 + akc;
        a0 = *reinterpret_cast<const float4*>(wp + 0);
        a1 = *reinterpret_cast<const float4*>(wp + 4);
        a2 = *reinterpret_cast<const float4*>(wp + 8);
        a3 = *reinterpret_cast<const float4*>(wp + 12);
        const float* xp = X + (size_t)brow * N_ + n0 + bnc;
        b0 = *reinterpret_cast<const float4*>(xp + 0);
        b1 = *reinterpret_cast<const float4*>(xp + 4);
    }

    #pragma unroll 1
    for (int t = 0; t < 8; ++t) {
        // pack stage -> smem (128-bit stores only)
        {
            uint32_t h0 = packh(a0.x, a0.y);
            uint32_t h1 = packh(a0.z, a0.w);
            uint32_t h2 = packh(a1.x, a1.y);
            uint32_t h3 = packh(a1.z, a1.w);
            uint32_t h4 = packh(a2.x, a2.y);
            uint32_t h5 = packh(a2.z, a2.w);
            uint32_t h6 = packh(a3.x, a3.y);
            uint32_t h7 = packh(a3.z, a3.w);
            const int ao = arow * G1_SA + akc;
            *reinterpret_cast<uint4*>(&sA[ao])     = make_uint4(h0, h1, h2, h3);
            *reinterpret_cast<uint4*>(&sA[ao + 8]) = make_uint4(h4, h5, h6, h7);
            uint32_t g0 = packh(b0.x, b0.y);
            uint32_t g1 = packh(b0.z, b0.w);
            uint32_t g2 = packh(b1.x, b1.y);
            uint32_t g3 = packh(b1.z, b1.w);
            *reinterpret_cast<uint4*>(&sB[brow * G1_SB + bnc]) = make_uint4(g0, g1, g2, g3);
        }
        __syncthreads();
        if (t < 7) {
            int kt = (t + 1) * 32;
            const float* wp = w + (size_t)(m0 + arow) * 256 + kt + akc;
            a0 = *reinterpret_cast<const float4*>(wp + 0);
            a1 = *reinterpret_cast<const float4*>(wp + 4);
            a2 = *reinterpret_cast<const float4*>(wp + 8);
            a3 = *reinterpret_cast<const float4*>(wp + 12);
            const float* xp = X + (size_t)(kt + brow) * N_ + n0 + bnc;
            b0 = *reinterpret_cast<const float4*>(xp + 0);
            b1 = *reinterpret_cast<const float4*>(xp + 4);
        }

        #pragma unroll
        for (int k2 = 0; k2 < 2; ++k2) {
            const int k16 = k2 * 16;
            uint32_t ah[2][4];
            #pragma unroll
            for (int mf = 0; mf < 2; ++mf) {
                int rowm = wm*32 + mf*16 + (lane & 15);
                int colk = k16 + (lane >> 4) * 8;
                ldsm_x4(ah[mf][0], ah[mf][1], ah[mf][2], ah[mf][3],
                        smem_u32(sA + rowm * G1_SA + colk));
            }
            uint32_t bh[2][4];
            #pragma unroll
            for (int p = 0; p < 2; ++p) {
                int krow = k16 + (lane & 15);
                int ncol = wn*32 + p*16 + (lane >> 4) * 8;
                ldsm_x4t(bh[p][0], bh[p][1], bh[p][2], bh[p][3],
                         smem_u32(sB + krow * G1_SB + ncol));
            }
            #pragma unroll
            for (int mf = 0; mf < 2; ++mf) {
                #pragma unroll
                for (int nf = 0; nf < 4; ++nf) {
                    const int p = nf >> 1, hh = (nf & 1) * 2;
                    mma_f16(acc[mf][nf][0], acc[mf][nf][1], acc[mf][nf][2], acc[mf][nf][3],
                            ah[mf][0], ah[mf][1], ah[mf][2], ah[mf][3],
                            bh[p][hh], bh[p][hh+1]);
                }
            }
        }
        __syncthreads();
    }

    // epilogue: q,k -> elu+1; v raw; fp32 stores
    const int type = m0 >> 8;  // 0=q, 1=k, 2=v
    #pragma unroll
    for (int mf = 0; mf < 2; ++mf) {
        int rbase = m0 + wm*32 + mf*16 + (lane >> 2);
        #pragma unroll
        for (int nf = 0; nf < 4; ++nf) {
            int c = n0 + wn*32 + nf*8 + (lane & 3) * 2;
            #pragma unroll
            for (int rh = 0; rh < 2; ++rh) {
                int r = rbase + rh * 8;
                float v0 = acc[mf][nf][rh*2 + 0];
                float v1 = acc[mf][nf][rh*2 + 1];
                if (type == 0) {
                    *reinterpret_cast<float2*>(&g_QK[((size_t)b*C_ + r)*N_ + c]) =
                        make_float2(elu1(v0), elu1(v1));
                } else if (type == 1) {
                    *reinterpret_cast<float2*>(&g_KK[((size_t)b*C_ + (r-256))*N_ + c]) =
                        make_float2(elu1(v0), elu1(v1));
                } else {
                    *reinterpret_cast<float2*>(&g_V[((size_t)b*C_ + (r-512))*N_ + c]) =
                        make_float2(v0, v1);
                }
            }
        }
    }
}

// ---------------------------------------------------------------- reduce (verbatim round 7)
__global__ __launch_bounds__(256) void k_reduce() {
    const int c = blockIdx.x, b = blockIdx.y;
    const float4* kk = reinterpret_cast<const float4*>(&g_KK[((size_t)b*C_ + c) * N_]);
    const float4* vv = reinterpret_cast<const float4*>(&g_V [((size_t)b*C_ + c) * N_]);
    float skv = 0.f, sk = 0.f;
    for (int i = threadIdx.x; i < 1024; i += 256) {
        float4 k4 = kk[i], v4 = vv[i];
        skv = fmaf(k4.x, v4.x, skv); skv = fmaf(k4.y, v4.y, skv);
        skv = fmaf(k4.z, v4.z, skv); skv = fmaf(k4.w, v4.w, skv);
        sk += k4.x + k4.y + k4.z + k4.w;
    }
    #pragma unroll
    for (int o = 16; o > 0; o >>= 1) {
        skv += __shfl_xor_sync(0xFFFFFFFFu, skv, o);
        sk  += __shfl_xor_sync(0xFFFFFFFFu, sk, o);
    }
    __shared__ float s1[8], s2[8];
    int w = threadIdx.x >> 5, l = threadIdx.x & 31;
    if (l == 0) { s1[w] = skv; s2[w] = sk; }
    __syncthreads();
    if (threadIdx.x == 0) {
        float a = 0.f, d = 0.f;
        #pragma unroll
        for (int i = 0; i < 8; ++i) { a += s1[i]; d += s2[i]; }
        g_s[b * C_ + c] = a / fmaxf(d, 1e-6f);
    }
}

// ---------------------------------------------------------------- GEMM2 + LN
// out[256,4096] = W_out[256,256] @ (s_row * QK)[256,4096] per batch, fused LN.
// Block 256(M)x32(N), kstep 16, 256 thr (4M x 2N warps; warp tile 64x16).
#define G2_SA 24
#define G2_SB 40

__global__ __launch_bounds__(256) void k_gemm2(const float* __restrict__ w_out,
                                               const float* __restrict__ gamma,
                                               const float* __restrict__ beta,
                                               float* __restrict__ out) {
    __shared__ __half sA[256 * G2_SA];
    __shared__ __half sB[16 * G2_SB];
    __shared__ float s_sm[256], g_sm[256], be_sm[256];
    __shared__ float red_s[32][32];
    __shared__ float red_q[32][32];
    __shared__ float mu_s[32], rs_s[32];

    const int tid = threadIdx.x, lane = tid & 31, wid = tid >> 5;
    const int wm = wid >> 1, wn = wid & 1;
    const int n0 = blockIdx.x * 32, b = blockIdx.y;
    const float* QK = g_QK + (size_t)b * C_ * N_;

    s_sm[tid]  = g_s[b * C_ + tid];
    g_sm[tid]  = gamma[tid];
    be_sm[tid] = beta[tid];
    __syncthreads();

    const int brow = (tid & 63) >> 2, bnc = (tid & 3) * 8;

    float acc[4][2][4];
    #pragma unroll
    for (int i = 0; i < 4; ++i)
        #pragma unroll
        for (int j = 0; j < 2; ++j)
            #pragma unroll
            for (int e = 0; e < 4; ++e) acc[i][j][e] = 0.f;

    float4 a0, a1, a2, a3, b0, b1;
    {
        const float* wp = w_out + (size_t)tid * 256;
        a0 = *reinterpret_cast<const float4*>(wp + 0);
        a1 = *reinterpret_cast<const float4*>(wp + 4);
        a2 = *reinterpret_cast<const float4*>(wp + 8);
        a3 = *reinterpret_cast<const float4*>(wp + 12);
        if (tid < 64) {
            const float* qp = QK + (size_t)brow * N_ + n0 + bnc;
            b0 = *reinterpret_cast<const float4*>(qp + 0);
            b1 = *reinterpret_cast<const float4*>(qp + 4);
        }
    }

    #pragma unroll 1
    for (int t = 0; t < 16; ++t) {
        const int kt = t * 16;
        {
            uint32_t h0 = packh(a0.x, a0.y);
            uint32_t h1 = packh(a0.z, a0.w);
            uint32_t h2 = packh(a1.x, a1.y);
            uint32_t h3 = packh(a1.z, a1.w);
            uint32_t h4 = packh(a2.x, a2.y);
            uint32_t h5 = packh(a2.z, a2.w);
            uint32_t h6 = packh(a3.x, a3.y);
            uint32_t h7 = packh(a3.z, a3.w);
            const int ao = tid * G2_SA;
            *reinterpret_cast<uint4*>(&sA[ao])     = make_uint4(h0, h1, h2, h3);
            *reinterpret_cast<uint4*>(&sA[ao + 8]) = make_uint4(h4, h5, h6, h7);
            if (tid < 64) {
                float sv = s_sm[kt + brow];
                uint32_t g0 = packh(b0.x * sv, b0.y * sv);
                uint32_t g1 = packh(b0.z * sv, b0.w * sv);
                uint32_t g2 = packh(b1.x * sv, b1.y * sv);
                uint32_t g3 = packh(b1.z * sv, b1.w * sv);
                *reinterpret_cast<uint4*>(&sB[brow * G2_SB + bnc]) = make_uint4(g0, g1, g2, g3);
            }
        }
        __syncthreads();
        if (t < 15) {
            int ktn = kt + 16;
            const float* wp = w_out + (size_t)tid * 256 + ktn;
            a0 = *reinterpret_cast<const float4*>(wp + 0);
            a1 = *reinterpret_cast<const float4*>(wp + 4);
            a2 = *reinterpret_cast<const float4*>(wp + 8);
            a3 = *reinterpret_cast<const float4*>(wp + 12);
            if (tid < 64) {
                const float* qp = QK + (size_t)(ktn + brow) * N_ + n0 + bnc;
                b0 = *reinterpret_cast<const float4*>(qp + 0);
                b1 = *reinterpret_cast<const float4*>(qp + 4);
            }
        }

        uint32_t ah[4][4];
        #pragma unroll
        for (int mf = 0; mf < 4; ++mf) {
            int rowm = wm*64 + mf*16 + (lane & 15);
            int colk = (lane >> 4) * 8;
            ldsm_x4(ah[mf][0], ah[mf][1], ah[mf][2], ah[mf][3],
                    smem_u32(sA + rowm * G2_SA + colk));
        }
        uint32_t bh[4];
        {
            int krow = lane & 15;
            int ncol = wn*16 + (lane >> 4) * 8;
            ldsm_x4t(bh[0], bh[1], bh[2], bh[3],
                     smem_u32(sB + krow * G2_SB + ncol));
        }
        #pragma unroll
        for (int mf = 0; mf < 4; ++mf) {
            #pragma unroll
            for (int nf = 0; nf < 2; ++nf) {
                const int hh = nf * 2;
                mma_f16(acc[mf][nf][0], acc[mf][nf][1], acc[mf][nf][2], acc[mf][nf][3],
                        ah[mf][0], ah[mf][1], ah[mf][2], ah[mf][3],
                        bh[hh], bh[hh+1]);
            }
        }
        __syncthreads();
    }

    // ---- fused LayerNorm over the 256 channels this block owns ----
    #pragma unroll
    for (int nf = 0; nf < 2; ++nf)
        #pragma unroll
        for (int e = 0; e < 2; ++e) {
            float s = 0.f, q = 0.f;
            #pragma unroll
            for (int mf = 0; mf < 4; ++mf)
                #pragma unroll
                for (int rh = 0; rh < 2; ++rh) {
                    float v = acc[mf][nf][rh*2 + e];
                    s += v; q = fmaf(v, v, q);
                }
            int col = wn*16 + nf*8 + (lane & 3)*2 + e;
            red_s[wm*8 + (lane >> 2)][col] = s;
            red_q[wm*8 + (lane >> 2)][col] = q;
        }
    __syncthreads();
    if (tid < 32) {
        float s = 0.f, q = 0.f;
        #pragma unroll
        for (int r = 0; r < 32; ++r) { s += red_s[r][tid]; q += red_q[r][tid]; }
        float mu  = s * (1.f / 256.f);
        float var = q * (1.f / 256.f) - mu * mu;
        mu_s[tid] = mu;
        rs_s[tid] = rsqrtf(var + 1e-5f);
    }
    __syncthreads();

    #pragma unroll
    for (int mf = 0; mf < 4; ++mf) {
        int rbase = wm*64 + mf*16 + (lane >> 2);
        #pragma unroll
        for (int nf = 0; nf < 2; ++nf) {
            int col = wn*16 + nf*8 + (lane & 3)*2;
            #pragma unroll
            for (int rh = 0; rh < 2; ++rh) {
                int r = rbase + rh*8;
                float ga = g_sm[r], be = be_sm[r];
                float v0 = (acc[mf][nf][rh*2+0] - mu_s[col])   * rs_s[col]   * ga + be;
                float v1 = (acc[mf][nf][rh*2+1] - mu_s[col+1]) * rs_s[col+1] * ga + be;
                *reinterpret_cast<float2*>(&out[((size_t)b*C_ + r)*N_ + n0 + col]) =
                    make_float2(v0, v1);
            }
        }
    }
}

// ----------------------------------------------------------------
extern "C" void kernel_launch(void* const* d_in, const int* in_sizes, int n_in,
                              void* d_out, int out_size) {
    const float* x     = (const float*)d_in[0];
    const float* w_qkv = (const float*)d_in[1];
    const float* w_out = (const float*)d_in[2];
    const float* gamma = (const float*)d_in[3];
    const float* beta  = (const float*)d_in[4];
    float* out = (float*)d_out;

    k_gemm1 <<<dim3(64, 6, 16), 256>>>(x, w_qkv);
    k_reduce<<<dim3(256, 16),   256>>>();
    k_gemm2 <<<dim3(128, 16),   256>>>(w_out, gamma, beta, out);
}

// round 12
// speedup vs baseline: 1.7890x; 1.1419x over previous
#include <cuda_runtime.h>
#include <cuda_fp16.h>
#include <math.h>
#include <stdint.h>

// Shapes: x [16,256,4096], w_qkv [768,256], w_out [256,256], gamma/beta [256]
#define C_ 256
#define N_ 4096

// scratch: 3 x 64MiB fp32 planes + s (identical to passing rounds 1/5/7/9)
__device__ float g_QK[16777216];   // elu(q)+1
__device__ float g_KK[16777216];   // elu(k)+1
__device__ float g_V [16777216];   // v
__device__ float g_s [4096];       // per (b,c) scale

// ---------------------------------------------------------------- helpers
__device__ __forceinline__ uint32_t smem_u32(const void* p) {
    return (uint32_t)__cvta_generic_to_shared(p);
}
__device__ __forceinline__ void ldsm_x4(uint32_t& r0, uint32_t& r1, uint32_t& r2, uint32_t& r3, uint32_t a) {
    asm volatile("ldmatrix.sync.aligned.m8n8.x4.shared.b16 {%0,%1,%2,%3}, [%4];"
                 : "=r"(r0), "=r"(r1), "=r"(r2), "=r"(r3) : "r"(a));
}
__device__ __forceinline__ void ldsm_x4t(uint32_t& r0, uint32_t& r1, uint32_t& r2, uint32_t& r3, uint32_t a) {
    asm volatile("ldmatrix.sync.aligned.m8n8.x4.trans.shared.b16 {%0,%1,%2,%3}, [%4];"
                 : "=r"(r0), "=r"(r1), "=r"(r2), "=r"(r3) : "r"(a));
}
__device__ __forceinline__ void mma_f16(float& d0, float& d1, float& d2, float& d3,
                                        uint32_t a0, uint32_t a1, uint32_t a2, uint32_t a3,
                                        uint32_t b0, uint32_t b1) {
    asm volatile("mma.sync.aligned.m16n8k16.row.col.f32.f16.f16.f32 "
                 "{%0,%1,%2,%3},{%4,%5,%6,%7},{%8,%9},{%0,%1,%2,%3};"
                 : "+f"(d0), "+f"(d1), "+f"(d2), "+f"(d3)
                 : "r"(a0), "r"(a1), "r"(a2), "r"(a3), "r"(b0), "r"(b1));
}
__device__ __forceinline__ float elu1(float v) { return v > 0.f ? v + 1.f : expf(v); }

// pack two fp32 -> fp16x2 (scalar integer ops only; no unions, no address-of)
__device__ __forceinline__ uint32_t packh(float a, float b) {
    return (uint32_t)__half_as_ushort(__float2half_rn(a))
         | ((uint32_t)__half_as_ushort(__float2half_rn(b)) << 16);
}

// ---------------------------------------------------------------- GEMM1
// C[768,4096] = W[768,256] @ X[256,4096] per batch, fp16 tensor cores.
// Block 128(M)x128(N), kstep 32, 256 thr (8 warps: 2M x 4N; warp tile 64x32).
#define G1_SA 40    // 32 k + 8 pad
#define G1_SB 136   // 128 n + 8 pad

__global__ __launch_bounds__(256) void k_gemm1(const float* __restrict__ x,
                                               const float* __restrict__ w) {
    __shared__ __half sA[128 * G1_SA];
    __shared__ __half sB[32 * G1_SB];

    const int tid = threadIdx.x, lane = tid & 31, wid = tid >> 5;
    const int wm = wid >> 2, wn = wid & 3;
    const int n0 = blockIdx.x * 128, m0 = blockIdx.y * 128, b = blockIdx.z;
    const float* X = x + (size_t)b * C_ * N_;

    // A stage: 128 rows x 32 k fp32; thread -> row = tid&127, kc = (tid>>7)*16
    const int arow = tid & 127, akc = (tid >> 7) * 16;
    // B stage: 32 rows x 128 n fp32; thread -> row = tid>>3, nc = (tid&7)*16
    const int brow = tid >> 3, bnc = (tid & 7) * 16;

    float acc[4][4][4];
    #pragma unroll
    for (int i = 0; i < 4; ++i)
        #pragma unroll
        for (int j = 0; j < 4; ++j)
            #pragma unroll
            for (int e = 0; e < 4; ++e) acc[i][j][e] = 0.f;

    float4 a0, a1, a2, a3, b0, b1, b2, b3;
    {
        const float* wp = w + (size_t)(m0 + arow) * 256 + akc;
        a0 = *reinterpret_cast<const float4*>(wp + 0);
        a1 = *reinterpret_cast<const float4*>(wp + 4);
        a2 = *reinterpret_cast<const float4*>(wp + 8);
        a3 = *reinterpret_cast<const float4*>(wp + 12);
        const float* xp = X + (size_t)brow * N_ + n0 + bnc;
        b0 = *reinterpret_cast<const float4*>(xp + 0);
        b1 = *reinterpret_cast<const float4*>(xp + 4);
        b2 = *reinterpret_cast<const float4*>(xp + 8);
        b3 = *reinterpret_cast<const float4*>(xp + 12);
    }

    #pragma unroll 1
    for (int t = 0; t < 8; ++t) {
        // pack stage -> smem (128-bit stores only)
        {
            const int ao = arow * G1_SA + akc;
            *reinterpret_cast<uint4*>(&sA[ao]) =
                make_uint4(packh(a0.x, a0.y), packh(a0.z, a0.w),
                           packh(a1.x, a1.y), packh(a1.z, a1.w));
            *reinterpret_cast<uint4*>(&sA[ao + 8]) =
                make_uint4(packh(a2.x, a2.y), packh(a2.z, a2.w),
                           packh(a3.x, a3.y), packh(a3.z, a3.w));
            const int bo = brow * G1_SB + bnc;
            *reinterpret_cast<uint4*>(&sB[bo]) =
                make_uint4(packh(b0.x, b0.y), packh(b0.z, b0.w),
                           packh(b1.x, b1.y), packh(b1.z, b1.w));
            *reinterpret_cast<uint4*>(&sB[bo + 8]) =
                make_uint4(packh(b2.x, b2.y), packh(b2.z, b2.w),
                           packh(b3.x, b3.y), packh(b3.z, b3.w));
        }
        __syncthreads();
        if (t < 7) {
            int kt = (t + 1) * 32;
            const float* wp = w + (size_t)(m0 + arow) * 256 + kt + akc;
            a0 = *reinterpret_cast<const float4*>(wp + 0);
            a1 = *reinterpret_cast<const float4*>(wp + 4);
            a2 = *reinterpret_cast<const float4*>(wp + 8);
            a3 = *reinterpret_cast<const float4*>(wp + 12);
            const float* xp = X + (size_t)(kt + brow) * N_ + n0 + bnc;
            b0 = *reinterpret_cast<const float4*>(xp + 0);
            b1 = *reinterpret_cast<const float4*>(xp + 4);
            b2 = *reinterpret_cast<const float4*>(xp + 8);
            b3 = *reinterpret_cast<const float4*>(xp + 12);
        }

        #pragma unroll
        for (int k2 = 0; k2 < 2; ++k2) {
            const int k16 = k2 * 16;
            uint32_t ah[4][4];
            #pragma unroll
            for (int mf = 0; mf < 4; ++mf) {
                int rowm = wm*64 + mf*16 + (lane & 15);
                int colk = k16 + (lane >> 4) * 8;
                ldsm_x4(ah[mf][0], ah[mf][1], ah[mf][2], ah[mf][3],
                        smem_u32(sA + rowm * G1_SA + colk));
            }
            uint32_t bh[2][4];
            #pragma unroll
            for (int p = 0; p < 2; ++p) {
                int krow = k16 + (lane & 15);
                int ncol = wn*32 + p*16 + (lane >> 4) * 8;
                ldsm_x4t(bh[p][0], bh[p][1], bh[p][2], bh[p][3],
                         smem_u32(sB + krow * G1_SB + ncol));
            }
            #pragma unroll
            for (int mf = 0; mf < 4; ++mf) {
                #pragma unroll
                for (int nf = 0; nf < 4; ++nf) {
                    const int p = nf >> 1, hh = (nf & 1) * 2;
                    mma_f16(acc[mf][nf][0], acc[mf][nf][1], acc[mf][nf][2], acc[mf][nf][3],
                            ah[mf][0], ah[mf][1], ah[mf][2], ah[mf][3],
                            bh[p][hh], bh[p][hh+1]);
                }
            }
        }
        __syncthreads();
    }

    // epilogue: q,k -> elu+1; v raw; fp32 stores
    const int type = m0 >> 8;  // 0=q, 1=k, 2=v
    #pragma unroll
    for (int mf = 0; mf < 4; ++mf) {
        int rbase = m0 + wm*64 + mf*16 + (lane >> 2);
        #pragma unroll
        for (int nf = 0; nf < 4; ++nf) {
            int c = n0 + wn*32 + nf*8 + (lane & 3) * 2;
            #pragma unroll
            for (int rh = 0; rh < 2; ++rh) {
                int r = rbase + rh * 8;
                float v0 = acc[mf][nf][rh*2 + 0];
                float v1 = acc[mf][nf][rh*2 + 1];
                if (type == 0) {
                    *reinterpret_cast<float2*>(&g_QK[((size_t)b*C_ + r)*N_ + c]) =
                        make_float2(elu1(v0), elu1(v1));
                } else if (type == 1) {
                    *reinterpret_cast<float2*>(&g_KK[((size_t)b*C_ + (r-256))*N_ + c]) =
                        make_float2(elu1(v0), elu1(v1));
                } else {
                    *reinterpret_cast<float2*>(&g_V[((size_t)b*C_ + (r-512))*N_ + c]) =
                        make_float2(v0, v1);
                }
            }
        }
    }
}

// ---------------------------------------------------------------- reduce (verbatim round 9)
__global__ __launch_bounds__(256) void k_reduce() {
    const int c = blockIdx.x, b = blockIdx.y;
    const float4* kk = reinterpret_cast<const float4*>(&g_KK[((size_t)b*C_ + c) * N_]);
    const float4* vv = reinterpret_cast<const float4*>(&g_V [((size_t)b*C_ + c) * N_]);
    float skv = 0.f, sk = 0.f;
    for (int i = threadIdx.x; i < 1024; i += 256) {
        float4 k4 = kk[i], v4 = vv[i];
        skv = fmaf(k4.x, v4.x, skv); skv = fmaf(k4.y, v4.y, skv);
        skv = fmaf(k4.z, v4.z, skv); skv = fmaf(k4.w, v4.w, skv);
        sk += k4.x + k4.y + k4.z + k4.w;
    }
    #pragma unroll
    for (int o = 16; o > 0; o >>= 1) {
        skv += __shfl_xor_sync(0xFFFFFFFFu, skv, o);
        sk  += __shfl_xor_sync(0xFFFFFFFFu, sk, o);
    }
    __shared__ float s1[8], s2[8];
    int w = threadIdx.x >> 5, l = threadIdx.x & 31;
    if (l == 0) { s1[w] = skv; s2[w] = sk; }
    __syncthreads();
    if (threadIdx.x == 0) {
        float a = 0.f, d = 0.f;
        #pragma unroll
        for (int i = 0; i < 8; ++i) { a += s1[i]; d += s2[i]; }
        g_s[b * C_ + c] = a / fmaxf(d, 1e-6f);
    }
}

// ---------------------------------------------------------------- GEMM2 + LN (verbatim round 9)
// out[256,4096] = W_out[256,256] @ (s_row * QK)[256,4096] per batch, fused LN.
// Block 256(M)x32(N), kstep 16, 256 thr (4M x 2N warps; warp tile 64x16).
#define G2_SA 24
#define G2_SB 40

__global__ __launch_bounds__(256) void k_gemm2(const float* __restrict__ w_out,
                                               const float* __restrict__ gamma,
                                               const float* __restrict__ beta,
                                               float* __restrict__ out) {
    __shared__ __half sA[256 * G2_SA];
    __shared__ __half sB[16 * G2_SB];
    __shared__ float s_sm[256], g_sm[256], be_sm[256];
    __shared__ float red_s[32][32];
    __shared__ float red_q[32][32];
    __shared__ float mu_s[32], rs_s[32];

    const int tid = threadIdx.x, lane = tid & 31, wid = tid >> 5;
    const int wm = wid >> 1, wn = wid & 1;
    const int n0 = blockIdx.x * 32, b = blockIdx.y;
    const float* QK = g_QK + (size_t)b * C_ * N_;

    s_sm[tid]  = g_s[b * C_ + tid];
    g_sm[tid]  = gamma[tid];
    be_sm[tid] = beta[tid];
    __syncthreads();

    const int brow = (tid & 63) >> 2, bnc = (tid & 3) * 8;

    float acc[4][2][4];
    #pragma unroll
    for (int i = 0; i < 4; ++i)
        #pragma unroll
        for (int j = 0; j < 2; ++j)
            #pragma unroll
            for (int e = 0; e < 4; ++e) acc[i][j][e] = 0.f;

    float4 a0, a1, a2, a3, b0, b1;
    {
        const float* wp = w_out + (size_t)tid * 256;
        a0 = *reinterpret_cast<const float4*>(wp + 0);
        a1 = *reinterpret_cast<const float4*>(wp + 4);
        a2 = *reinterpret_cast<const float4*>(wp + 8);
        a3 = *reinterpret_cast<const float4*>(wp + 12);
        if (tid < 64) {
            const float* qp = QK + (size_t)brow * N_ + n0 + bnc;
            b0 = *reinterpret_cast<const float4*>(qp + 0);
            b1 = *reinterpret_cast<const float4*>(qp + 4);
        }
    }

    #pragma unroll 1
    for (int t = 0; t < 16; ++t) {
        const int kt = t * 16;
        {
            uint32_t h0 = packh(a0.x, a0.y);
            uint32_t h1 = packh(a0.z, a0.w);
            uint32_t h2 = packh(a1.x, a1.y);
            uint32_t h3 = packh(a1.z, a1.w);
            uint32_t h4 = packh(a2.x, a2.y);
            uint32_t h5 = packh(a2.z, a2.w);
            uint32_t h6 = packh(a3.x, a3.y);
            uint32_t h7 = packh(a3.z, a3.w);
            const int ao = tid * G2_SA;
            *reinterpret_cast<uint4*>(&sA[ao])     = make_uint4(h0, h1, h2, h3);
            *reinterpret_cast<uint4*>(&sA[ao + 8]) = make_uint4(h4, h5, h6, h7);
            if (tid < 64) {
                float sv = s_sm[kt + brow];
                uint32_t g0 = packh(b0.x * sv, b0.y * sv);
                uint32_t g1 = packh(b0.z * sv, b0.w * sv);
                uint32_t g2 = packh(b1.x * sv, b1.y * sv);
                uint32_t g3 = packh(b1.z * sv, b1.w * sv);
                *reinterpret_cast<uint4*>(&sB[brow * G2_SB + bnc]) = make_uint4(g0, g1, g2, g3);
            }
        }
        __syncthreads();
        if (t < 15) {
            int ktn = kt + 16;
            const float* wp = w_out + (size_t)tid * 256 + ktn;
            a0 = *reinterpret_cast<const float4*>(wp + 0);
            a1 = *reinterpret_cast<const float4*>(wp + 4);
            a2 = *reinterpret_cast<const float4*>(wp + 8);
            a3 = *reinterpret_cast<const float4*>(wp + 12);
            if (tid < 64) {
                const float* qp = QK + (size_t)(ktn + brow) * N_ + n0 + bnc;
                b0 = *reinterpret_cast<const float4*>(qp + 0);
                b1 = *reinterpret_cast<const float4*>(qp + 4);
            }
        }

        uint32_t ah[4][4];
        #pragma unroll
        for (int mf = 0; mf < 4; ++mf) {
            int rowm = wm*64 + mf*16 + (lane & 15);
            int colk = (lane >> 4) * 8;
            ldsm_x4(ah[mf][0], ah[mf][1], ah[mf][2], ah[mf][3],
                    smem_u32(sA + rowm * G2_SA + colk));
        }
        uint32_t bh[4];
        {
            int krow = lane & 15;
            int ncol = wn*16 + (lane >> 4) * 8;
            ldsm_x4t(bh[0], bh[1], bh[2], bh[3],
                     smem_u32(sB + krow * G2_SB + ncol));
        }
        #pragma unroll
        for (int mf = 0; mf < 4; ++mf) {
            #pragma unroll
            for (int nf = 0; nf < 2; ++nf) {
                const int hh = nf * 2;
                mma_f16(acc[mf][nf][0], acc[mf][nf][1], acc[mf][nf][2], acc[mf][nf][3],
                        ah[mf][0], ah[mf][1], ah[mf][2], ah[mf][3],
                        bh[hh], bh[hh+1]);
            }
        }
        __syncthreads();
    }

    // ---- fused LayerNorm over the 256 channels this block owns ----
    #pragma unroll
    for (int nf = 0; nf < 2; ++nf)
        #pragma unroll
        for (int e = 0; e < 2; ++e) {
            float s = 0.f, q = 0.f;
            #pragma unroll
            for (int mf = 0; mf < 4; ++mf)
                #pragma unroll
                for (int rh = 0; rh < 2; ++rh) {
                    float v = acc[mf][nf][rh*2 + e];
                    s += v; q = fmaf(v, v, q);
                }
            int col = wn*16 + nf*8 + (lane & 3)*2 + e;
            red_s[wm*8 + (lane >> 2)][col] = s;
            red_q[wm*8 + (lane >> 2)][col] = q;
        }
    __syncthreads();
    if (tid < 32) {
        float s = 0.f, q = 0.f;
        #pragma unroll
        for (int r = 0; r < 32; ++r) { s += red_s[r][tid]; q += red_q[r][tid]; }
        float mu  = s * (1.f / 256.f);
        float var = q * (1.f / 256.f) - mu * mu;
        mu_s[tid] = mu;
        rs_s[tid] = rsqrtf(var + 1e-5f);
    }
    __syncthreads();

    #pragma unroll
    for (int mf = 0; mf < 4; ++mf) {
        int rbase = wm*64 + mf*16 + (lane >> 2);
        #pragma unroll
        for (int nf = 0; nf < 2; ++nf) {
            int col = wn*16 + nf*8 + (lane & 3)*2;
            #pragma unroll
            for (int rh = 0; rh < 2; ++rh) {
                int r = rbase + rh*8;
                float ga = g_sm[r], be = be_sm[r];
                float v0 = (acc[mf][nf][rh*2+0] - mu_s[col])   * rs_s[col]   * ga + be;
                float v1 = (acc[mf][nf][rh*2+1] - mu_s[col+1]) * rs_s[col+1] * ga + be;
                *reinterpret_cast<float2*>(&out[((size_t)b*C_ + r)*N_ + n0 + col]) =
                    make_float2(v0, v1);
            }
        }
    }
}

// ----------------------------------------------------------------
extern "C" void kernel_launch(void* const* d_in, const int* in_sizes, int n_in,
                              void* d_out, int out_size) {
    const float* x     = (const float*)d_in[0];
    const float* w_qkv = (const float*)d_in[1];
    const float* w_out = (const float*)d_in[2];
    const float* gamma = (const float*)d_in[3];
    const float* beta  = (const float*)d_in[4];
    float* out = (float*)d_out;

    k_gemm1 <<<dim3(32, 6, 16), 256>>>(x, w_qkv);
    k_reduce<<<dim3(256, 16),   256>>>();
    k_gemm2 <<<dim3(128, 16),   256>>>(w_out, gamma, beta, out);
}

// round 13
// speedup vs baseline: 2.1180x; 1.1839x over previous
#include <cuda_runtime.h>
#include <cuda_fp16.h>
#include <math.h>
#include <stdint.h>

// Shapes: x [16,256,4096], w_qkv [768,256], w_out [256,256], gamma/beta [256]
#define C_ 256
#define N_ 4096

// scratch: 3 x 64MiB fp32 planes + s (identical to all passing rounds)
__device__ float g_QK[16777216];   // elu(q)+1
__device__ float g_KK[16777216];   // elu(k)+1
__device__ float g_V [16777216];   // v
__device__ float g_s [4096];       // per (b,c) scale

// ---------------------------------------------------------------- helpers
__device__ __forceinline__ uint32_t smem_u32(const void* p) {
    return (uint32_t)__cvta_generic_to_shared(p);
}
__device__ __forceinline__ void ldsm_x4(uint32_t& r0, uint32_t& r1, uint32_t& r2, uint32_t& r3, uint32_t a) {
    asm volatile("ldmatrix.sync.aligned.m8n8.x4.shared.b16 {%0,%1,%2,%3}, [%4];"
                 : "=r"(r0), "=r"(r1), "=r"(r2), "=r"(r3) : "r"(a));
}
__device__ __forceinline__ void ldsm_x4t(uint32_t& r0, uint32_t& r1, uint32_t& r2, uint32_t& r3, uint32_t a) {
    asm volatile("ldmatrix.sync.aligned.m8n8.x4.trans.shared.b16 {%0,%1,%2,%3}, [%4];"
                 : "=r"(r0), "=r"(r1), "=r"(r2), "=r"(r3) : "r"(a));
}
__device__ __forceinline__ void mma_f16(float& d0, float& d1, float& d2, float& d3,
                                        uint32_t a0, uint32_t a1, uint32_t a2, uint32_t a3,
                                        uint32_t b0, uint32_t b1) {
    asm volatile("mma.sync.aligned.m16n8k16.row.col.f32.f16.f16.f32 "
                 "{%0,%1,%2,%3},{%4,%5,%6,%7},{%8,%9},{%0,%1,%2,%3};"
                 : "+f"(d0), "+f"(d1), "+f"(d2), "+f"(d3)
                 : "r"(a0), "r"(a1), "r"(a2), "r"(a3), "r"(b0), "r"(b1));
}
__device__ __forceinline__ float elu1(float v) { return v > 0.f ? v + 1.f : expf(v); }

// pack two fp32 -> fp16x2 (scalar integer ops only; no unions, no address-of)
__device__ __forceinline__ uint32_t packh(float a, float b) {
    return (uint32_t)__half_as_ushort(__float2half_rn(a))
         | ((uint32_t)__half_as_ushort(__float2half_rn(b)) << 16);
}

// ---------------------------------------------------------------- GEMM1 (verbatim round 12)
// C[768,4096] = W[768,256] @ X[256,4096] per batch, fp16 tensor cores.
// Block 128(M)x128(N), kstep 32, 256 thr (8 warps: 2M x 4N; warp tile 64x32).
#define G1_SA 40    // 32 k + 8 pad
#define G1_SB 136   // 128 n + 8 pad

__global__ __launch_bounds__(256) void k_gemm1(const float* __restrict__ x,
                                               const float* __restrict__ w) {
    __shared__ __half sA[128 * G1_SA];
    __shared__ __half sB[32 * G1_SB];

    const int tid = threadIdx.x, lane = tid & 31, wid = tid >> 5;
    const int wm = wid >> 2, wn = wid & 3;
    const int n0 = blockIdx.x * 128, m0 = blockIdx.y * 128, b = blockIdx.z;
    const float* X = x + (size_t)b * C_ * N_;

    const int arow = tid & 127, akc = (tid >> 7) * 16;
    const int brow = tid >> 3, bnc = (tid & 7) * 16;

    float acc[4][4][4];
    #pragma unroll
    for (int i = 0; i < 4; ++i)
        #pragma unroll
        for (int j = 0; j < 4; ++j)
            #pragma unroll
            for (int e = 0; e < 4; ++e) acc[i][j][e] = 0.f;

    float4 a0, a1, a2, a3, b0, b1, b2, b3;
    {
        const float* wp = w + (size_t)(m0 + arow) * 256 + akc;
        a0 = *reinterpret_cast<const float4*>(wp + 0);
        a1 = *reinterpret_cast<const float4*>(wp + 4);
        a2 = *reinterpret_cast<const float4*>(wp + 8);
        a3 = *reinterpret_cast<const float4*>(wp + 12);
        const float* xp = X + (size_t)brow * N_ + n0 + bnc;
        b0 = *reinterpret_cast<const float4*>(xp + 0);
        b1 = *reinterpret_cast<const float4*>(xp + 4);
        b2 = *reinterpret_cast<const float4*>(xp + 8);
        b3 = *reinterpret_cast<const float4*>(xp + 12);
    }

    #pragma unroll 1
    for (int t = 0; t < 8; ++t) {
        {
            const int ao = arow * G1_SA + akc;
            *reinterpret_cast<uint4*>(&sA[ao]) =
                make_uint4(packh(a0.x, a0.y), packh(a0.z, a0.w),
                           packh(a1.x, a1.y), packh(a1.z, a1.w));
            *reinterpret_cast<uint4*>(&sA[ao + 8]) =
                make_uint4(packh(a2.x, a2.y), packh(a2.z, a2.w),
                           packh(a3.x, a3.y), packh(a3.z, a3.w));
            const int bo = brow * G1_SB + bnc;
            *reinterpret_cast<uint4*>(&sB[bo]) =
                make_uint4(packh(b0.x, b0.y), packh(b0.z, b0.w),
                           packh(b1.x, b1.y), packh(b1.z, b1.w));
            *reinterpret_cast<uint4*>(&sB[bo + 8]) =
                make_uint4(packh(b2.x, b2.y), packh(b2.z, b2.w),
                           packh(b3.x, b3.y), packh(b3.z, b3.w));
        }
        __syncthreads();
        if (t < 7) {
            int kt = (t + 1) * 32;
            const float* wp = w + (size_t)(m0 + arow) * 256 + kt + akc;
            a0 = *reinterpret_cast<const float4*>(wp + 0);
            a1 = *reinterpret_cast<const float4*>(wp + 4);
            a2 = *reinterpret_cast<const float4*>(wp + 8);
            a3 = *reinterpret_cast<const float4*>(wp + 12);
            const float* xp = X + (size_t)(kt + brow) * N_ + n0 + bnc;
            b0 = *reinterpret_cast<const float4*>(xp + 0);
            b1 = *reinterpret_cast<const float4*>(xp + 4);
            b2 = *reinterpret_cast<const float4*>(xp + 8);
            b3 = *reinterpret_cast<const float4*>(xp + 12);
        }

        #pragma unroll
        for (int k2 = 0; k2 < 2; ++k2) {
            const int k16 = k2 * 16;
            uint32_t ah[4][4];
            #pragma unroll
            for (int mf = 0; mf < 4; ++mf) {
                int rowm = wm*64 + mf*16 + (lane & 15);
                int colk = k16 + (lane >> 4) * 8;
                ldsm_x4(ah[mf][0], ah[mf][1], ah[mf][2], ah[mf][3],
                        smem_u32(sA + rowm * G1_SA + colk));
            }
            uint32_t bh[2][4];
            #pragma unroll
            for (int p = 0; p < 2; ++p) {
                int krow = k16 + (lane & 15);
                int ncol = wn*32 + p*16 + (lane >> 4) * 8;
                ldsm_x4t(bh[p][0], bh[p][1], bh[p][2], bh[p][3],
                         smem_u32(sB + krow * G1_SB + ncol));
            }
            #pragma unroll
            for (int mf = 0; mf < 4; ++mf) {
                #pragma unroll
                for (int nf = 0; nf < 4; ++nf) {
                    const int p = nf >> 1, hh = (nf & 1) * 2;
                    mma_f16(acc[mf][nf][0], acc[mf][nf][1], acc[mf][nf][2], acc[mf][nf][3],
                            ah[mf][0], ah[mf][1], ah[mf][2], ah[mf][3],
                            bh[p][hh], bh[p][hh+1]);
                }
            }
        }
        __syncthreads();
    }

    const int type = m0 >> 8;  // 0=q, 1=k, 2=v
    #pragma unroll
    for (int mf = 0; mf < 4; ++mf) {
        int rbase = m0 + wm*64 + mf*16 + (lane >> 2);
        #pragma unroll
        for (int nf = 0; nf < 4; ++nf) {
            int c = n0 + wn*32 + nf*8 + (lane & 3) * 2;
            #pragma unroll
            for (int rh = 0; rh < 2; ++rh) {
                int r = rbase + rh * 8;
                float v0 = acc[mf][nf][rh*2 + 0];
                float v1 = acc[mf][nf][rh*2 + 1];
                if (type == 0) {
                    *reinterpret_cast<float2*>(&g_QK[((size_t)b*C_ + r)*N_ + c]) =
                        make_float2(elu1(v0), elu1(v1));
                } else if (type == 1) {
                    *reinterpret_cast<float2*>(&g_KK[((size_t)b*C_ + (r-256))*N_ + c]) =
                        make_float2(elu1(v0), elu1(v1));
                } else {
                    *reinterpret_cast<float2*>(&g_V[((size_t)b*C_ + (r-512))*N_ + c]) =
                        make_float2(v0, v1);
                }
            }
        }
    }
}

// ---------------------------------------------------------------- reduce (verbatim)
__global__ __launch_bounds__(256) void k_reduce() {
    const int c = blockIdx.x, b = blockIdx.y;
    const float4* kk = reinterpret_cast<const float4*>(&g_KK[((size_t)b*C_ + c) * N_]);
    const float4* vv = reinterpret_cast<const float4*>(&g_V [((size_t)b*C_ + c) * N_]);
    float skv = 0.f, sk = 0.f;
    for (int i = threadIdx.x; i < 1024; i += 256) {
        float4 k4 = kk[i], v4 = vv[i];
        skv = fmaf(k4.x, v4.x, skv); skv = fmaf(k4.y, v4.y, skv);
        skv = fmaf(k4.z, v4.z, skv); skv = fmaf(k4.w, v4.w, skv);
        sk += k4.x + k4.y + k4.z + k4.w;
    }
    #pragma unroll
    for (int o = 16; o > 0; o >>= 1) {
        skv += __shfl_xor_sync(0xFFFFFFFFu, skv, o);
        sk  += __shfl_xor_sync(0xFFFFFFFFu, sk, o);
    }
    __shared__ float s1[8], s2[8];
    int w = threadIdx.x >> 5, l = threadIdx.x & 31;
    if (l == 0) { s1[w] = skv; s2[w] = sk; }
    __syncthreads();
    if (threadIdx.x == 0) {
        float a = 0.f, d = 0.f;
        #pragma unroll
        for (int i = 0; i < 8; ++i) { a += s1[i]; d += s2[i]; }
        g_s[b * C_ + c] = a / fmaxf(d, 1e-6f);
    }
}

// ---------------------------------------------------------------- GEMM2 + LN (widened)
// out[256,4096] = W_out[256,256] @ (s_row * QK)[256,4096] per batch, fused LN.
// Block 256(M)x64(N), kstep 16, 256 thr (8 warps: 4M x 2N; warp tile 64x32).
#define G2_SA 24   // 16 k + 8 pad
#define G2_SB 72   // 64 n + 8 pad

__global__ __launch_bounds__(256) void k_gemm2(const float* __restrict__ w_out,
                                               const float* __restrict__ gamma,
                                               const float* __restrict__ beta,
                                               float* __restrict__ out) {
    __shared__ __half sA[256 * G2_SA];
    __shared__ __half sB[16 * G2_SB];
    __shared__ float s_sm[256], g_sm[256], be_sm[256];
    __shared__ float red_s[32][64];
    __shared__ float red_q[32][64];
    __shared__ float mu_s[64], rs_s[64];

    const int tid = threadIdx.x, lane = tid & 31, wid = tid >> 5;
    const int wm = wid >> 1, wn = wid & 1;
    const int n0 = blockIdx.x * 64, b = blockIdx.y;
    const float* QK = g_QK + (size_t)b * C_ * N_;

    s_sm[tid]  = g_s[b * C_ + tid];
    g_sm[tid]  = gamma[tid];
    be_sm[tid] = beta[tid];
    __syncthreads();

    // A stage: 256 rows x 16 k; thread -> row tid, 16 consecutive k (4 float4)
    // B stage: 16 rows x 64 n; tid<128 -> brow = (tid&127)>>3, bnc = (tid&7)*8 (2 float4)
    const int brow = (tid & 127) >> 3, bnc = (tid & 7) * 8;

    float acc[4][4][4];
    #pragma unroll
    for (int i = 0; i < 4; ++i)
        #pragma unroll
        for (int j = 0; j < 4; ++j)
            #pragma unroll
            for (int e = 0; e < 4; ++e) acc[i][j][e] = 0.f;

    float4 a0, a1, a2, a3, b0, b1;
    {
        const float* wp = w_out + (size_t)tid * 256;
        a0 = *reinterpret_cast<const float4*>(wp + 0);
        a1 = *reinterpret_cast<const float4*>(wp + 4);
        a2 = *reinterpret_cast<const float4*>(wp + 8);
        a3 = *reinterpret_cast<const float4*>(wp + 12);
        if (tid < 128) {
            const float* qp = QK + (size_t)brow * N_ + n0 + bnc;
            b0 = *reinterpret_cast<const float4*>(qp + 0);
            b1 = *reinterpret_cast<const float4*>(qp + 4);
        }
    }

    #pragma unroll 1
    for (int t = 0; t < 16; ++t) {
        const int kt = t * 16;
        {
            const int ao = tid * G2_SA;
            *reinterpret_cast<uint4*>(&sA[ao]) =
                make_uint4(packh(a0.x, a0.y), packh(a0.z, a0.w),
                           packh(a1.x, a1.y), packh(a1.z, a1.w));
            *reinterpret_cast<uint4*>(&sA[ao + 8]) =
                make_uint4(packh(a2.x, a2.y), packh(a2.z, a2.w),
                           packh(a3.x, a3.y), packh(a3.z, a3.w));
            if (tid < 128) {
                float sv = s_sm[kt + brow];
                *reinterpret_cast<uint4*>(&sB[brow * G2_SB + bnc]) =
                    make_uint4(packh(b0.x * sv, b0.y * sv), packh(b0.z * sv, b0.w * sv),
                               packh(b1.x * sv, b1.y * sv), packh(b1.z * sv, b1.w * sv));
            }
        }
        __syncthreads();
        if (t < 15) {
            int ktn = kt + 16;
            const float* wp = w_out + (size_t)tid * 256 + ktn;
            a0 = *reinterpret_cast<const float4*>(wp + 0);
            a1 = *reinterpret_cast<const float4*>(wp + 4);
            a2 = *reinterpret_cast<const float4*>(wp + 8);
            a3 = *reinterpret_cast<const float4*>(wp + 12);
            if (tid < 128) {
                const float* qp = QK + (size_t)(ktn + brow) * N_ + n0 + bnc;
                b0 = *reinterpret_cast<const float4*>(qp + 0);
                b1 = *reinterpret_cast<const float4*>(qp + 4);
            }
        }

        uint32_t ah[4][4];
        #pragma unroll
        for (int mf = 0; mf < 4; ++mf) {
            int rowm = wm*64 + mf*16 + (lane & 15);
            int colk = (lane >> 4) * 8;
            ldsm_x4(ah[mf][0], ah[mf][1], ah[mf][2], ah[mf][3],
                    smem_u32(sA + rowm * G2_SA + colk));
        }
        uint32_t bh[2][4];
        #pragma unroll
        for (int p = 0; p < 2; ++p) {
            int krow = lane & 15;
            int ncol = wn*32 + p*16 + (lane >> 4) * 8;
            ldsm_x4t(bh[p][0], bh[p][1], bh[p][2], bh[p][3],
                     smem_u32(sB + krow * G2_SB + ncol));
        }
        #pragma unroll
        for (int mf = 0; mf < 4; ++mf) {
            #pragma unroll
            for (int nf = 0; nf < 4; ++nf) {
                const int p = nf >> 1, hh = (nf & 1) * 2;
                mma_f16(acc[mf][nf][0], acc[mf][nf][1], acc[mf][nf][2], acc[mf][nf][3],
                        ah[mf][0], ah[mf][1], ah[mf][2], ah[mf][3],
                        bh[p][hh], bh[p][hh+1]);
            }
        }
        __syncthreads();
    }

    // ---- fused LayerNorm over the 256 channels this block owns ----
    #pragma unroll
    for (int nf = 0; nf < 4; ++nf)
        #pragma unroll
        for (int e = 0; e < 2; ++e) {
            float s = 0.f, q = 0.f;
            #pragma unroll
            for (int mf = 0; mf < 4; ++mf)
                #pragma unroll
                for (int rh = 0; rh < 2; ++rh) {
                    float v = acc[mf][nf][rh*2 + e];
                    s += v; q = fmaf(v, v, q);
                }
            int col = wn*32 + nf*8 + (lane & 3)*2 + e;
            red_s[wm*8 + (lane >> 2)][col] = s;
            red_q[wm*8 + (lane >> 2)][col] = q;
        }
    __syncthreads();
    if (tid < 64) {
        float s = 0.f, q = 0.f;
        #pragma unroll
        for (int r = 0; r < 32; ++r) { s += red_s[r][tid]; q += red_q[r][tid]; }
        float mu  = s * (1.f / 256.f);
        float var = q * (1.f / 256.f) - mu * mu;
        mu_s[tid] = mu;
        rs_s[tid] = rsqrtf(var + 1e-5f);
    }
    __syncthreads();

    #pragma unroll
    for (int mf = 0; mf < 4; ++mf) {
        int rbase = wm*64 + mf*16 + (lane >> 2);
        #pragma unroll
        for (int nf = 0; nf < 4; ++nf) {
            int col = wn*32 + nf*8 + (lane & 3)*2;
            #pragma unroll
            for (int rh = 0; rh < 2; ++rh) {
                int r = rbase + rh*8;
                float ga = g_sm[r], be = be_sm[r];
                float v0 = (acc[mf][nf][rh*2+0] - mu_s[col])   * rs_s[col]   * ga + be;
                float v1 = (acc[mf][nf][rh*2+1] - mu_s[col+1]) * rs_s[col+1] * ga + be;
                *reinterpret_cast<float2*>(&out[((size_t)b*C_ + r)*N_ + n0 + col]) =
                    make_float2(v0, v1);
            }
        }
    }
}

// ----------------------------------------------------------------
extern "C" void kernel_launch(void* const* d_in, const int* in_sizes, int n_in,
                              void* d_out, int out_size) {
    const float* x     = (const float*)d_in[0];
    const float* w_qkv = (const float*)d_in[1];
    const float* w_out = (const float*)d_in[2];
    const float* gamma = (const float*)d_in[3];
    const float* beta  = (const float*)d_in[4];
    float* out = (float*)d_out;

    k_gemm1 <<<dim3(32, 6, 16), 256>>>(x, w_qkv);
    k_reduce<<<dim3(256, 16),   256>>>();
    k_gemm2 <<<dim3(64, 16),    256>>>(w_out, gamma, beta, out);
}

// round 15
// speedup vs baseline: 2.1796x; 1.0291x over previous
#include <cuda_runtime.h>
#include <cuda_fp16.h>
#include <math.h>
#include <stdint.h>

// Shapes: x [16,256,4096], w_qkv [768,256], w_out [256,256], gamma/beta [256]
#define C_ 256
#define N_ 4096

// scratch: packed fp16x2 intermediates in plain uint32 arrays + fp32 s.
// EXACTLY 3 kernel launches (hard constraint learned rounds 1-14).
__device__ uint32_t g_QKp[8388608];   // elu(q)+1 packed fp16x2
__device__ uint32_t g_KKp[8388608];   // elu(k)+1 packed
__device__ uint32_t g_Vp [8388608];   // v packed
__device__ float    g_s  [4096];      // per (b,c) scale

// ---------------------------------------------------------------- helpers
__device__ __forceinline__ uint32_t smem_u32(const void* p) {
    return (uint32_t)__cvta_generic_to_shared(p);
}
__device__ __forceinline__ void ldsm_x4(uint32_t& r0, uint32_t& r1, uint32_t& r2, uint32_t& r3, uint32_t a) {
    asm volatile("ldmatrix.sync.aligned.m8n8.x4.shared.b16 {%0,%1,%2,%3}, [%4];"
                 : "=r"(r0), "=r"(r1), "=r"(r2), "=r"(r3) : "r"(a));
}
__device__ __forceinline__ void ldsm_x4t(uint32_t& r0, uint32_t& r1, uint32_t& r2, uint32_t& r3, uint32_t a) {
    asm volatile("ldmatrix.sync.aligned.m8n8.x4.trans.shared.b16 {%0,%1,%2,%3}, [%4];"
                 : "=r"(r0), "=r"(r1), "=r"(r2), "=r"(r3) : "r"(a));
}
__device__ __forceinline__ void mma_f16(float& d0, float& d1, float& d2, float& d3,
                                        uint32_t a0, uint32_t a1, uint32_t a2, uint32_t a3,
                                        uint32_t b0, uint32_t b1) {
    asm volatile("mma.sync.aligned.m16n8k16.row.col.f32.f16.f16.f32 "
                 "{%0,%1,%2,%3},{%4,%5,%6,%7},{%8,%9},{%0,%1,%2,%3};"
                 : "+f"(d0), "+f"(d1), "+f"(d2), "+f"(d3)
                 : "r"(a0), "r"(a1), "r"(a2), "r"(a3), "r"(b0), "r"(b1));
}
__device__ __forceinline__ float elu1(float v) { return v > 0.f ? v + 1.f : expf(v); }

// pack two fp32 -> fp16x2 (scalar integer ops only; no unions, no address-of)
__device__ __forceinline__ uint32_t packh(float a, float b) {
    return (uint32_t)__half_as_ushort(__float2half_rn(a))
         | ((uint32_t)__half_as_ushort(__float2half_rn(b)) << 16);
}
__device__ __forceinline__ float lo16(uint32_t w) {
    return __half2float(__ushort_as_half((unsigned short)(w & 0xFFFFu)));
}
__device__ __forceinline__ float hi16(uint32_t w) {
    return __half2float(__ushort_as_half((unsigned short)(w >> 16)));
}

// ---------------------------------------------------------------- GEMM1
// C[768,4096] = W[768,256] @ X[256,4096] per batch, fp16 tensor cores.
// Block 128(M)x128(N), kstep 32, 256 thr (8 warps: 2M x 4N; warp tile 64x32).
// fp32 inputs, packh at staging (proven round 12/13); packed fp16 outputs.
#define G1_SA 40    // 32 k + 8 pad
#define G1_SB 136   // 128 n + 8 pad

__global__ __launch_bounds__(256) void k_gemm1(const float* __restrict__ x,
                                               const float* __restrict__ w) {
    __shared__ __half sA[128 * G1_SA];
    __shared__ __half sB[32 * G1_SB];

    const int tid = threadIdx.x, lane = tid & 31, wid = tid >> 5;
    const int wm = wid >> 2, wn = wid & 3;
    const int n0 = blockIdx.x * 128, m0 = blockIdx.y * 128, b = blockIdx.z;
    const float* X = x + (size_t)b * C_ * N_;

    const int arow = tid & 127, akc = (tid >> 7) * 16;
    const int brow = tid >> 3, bnc = (tid & 7) * 16;

    float acc[4][4][4];
    #pragma unroll
    for (int i = 0; i < 4; ++i)
        #pragma unroll
        for (int j = 0; j < 4; ++j)
            #pragma unroll
            for (int e = 0; e < 4; ++e) acc[i][j][e] = 0.f;

    float4 a0, a1, a2, a3, b0, b1, b2, b3;
    {
        const float* wp = w + (size_t)(m0 + arow) * 256 + akc;
        a0 = *reinterpret_cast<const float4*>(wp + 0);
        a1 = *reinterpret_cast<const float4*>(wp + 4);
        a2 = *reinterpret_cast<const float4*>(wp + 8);
        a3 = *reinterpret_cast<const float4*>(wp + 12);
        const float* xp = X + (size_t)brow * N_ + n0 + bnc;
        b0 = *reinterpret_cast<const float4*>(xp + 0);
        b1 = *reinterpret_cast<const float4*>(xp + 4);
        b2 = *reinterpret_cast<const float4*>(xp + 8);
        b3 = *reinterpret_cast<const float4*>(xp + 12);
    }

    #pragma unroll 1
    for (int t = 0; t < 8; ++t) {
        {
            const int ao = arow * G1_SA + akc;
            *reinterpret_cast<uint4*>(&sA[ao]) =
                make_uint4(packh(a0.x, a0.y), packh(a0.z, a0.w),
                           packh(a1.x, a1.y), packh(a1.z, a1.w));
            *reinterpret_cast<uint4*>(&sA[ao + 8]) =
                make_uint4(packh(a2.x, a2.y), packh(a2.z, a2.w),
                           packh(a3.x, a3.y), packh(a3.z, a3.w));
            const int bo = brow * G1_SB + bnc;
            *reinterpret_cast<uint4*>(&sB[bo]) =
                make_uint4(packh(b0.x, b0.y), packh(b0.z, b0.w),
                           packh(b1.x, b1.y), packh(b1.z, b1.w));
            *reinterpret_cast<uint4*>(&sB[bo + 8]) =
                make_uint4(packh(b2.x, b2.y), packh(b2.z, b2.w),
                           packh(b3.x, b3.y), packh(b3.z, b3.w));
        }
        __syncthreads();
        if (t < 7) {
            int kt = (t + 1) * 32;
            const float* wp = w + (size_t)(m0 + arow) * 256 + kt + akc;
            a0 = *reinterpret_cast<const float4*>(wp + 0);
            a1 = *reinterpret_cast<const float4*>(wp + 4);
            a2 = *reinterpret_cast<const float4*>(wp + 8);
            a3 = *reinterpret_cast<const float4*>(wp + 12);
            const float* xp = X + (size_t)(kt + brow) * N_ + n0 + bnc;
            b0 = *reinterpret_cast<const float4*>(xp + 0);
            b1 = *reinterpret_cast<const float4*>(xp + 4);
            b2 = *reinterpret_cast<const float4*>(xp + 8);
            b3 = *reinterpret_cast<const float4*>(xp + 12);
        }

        #pragma unroll
        for (int k2 = 0; k2 < 2; ++k2) {
            const int k16 = k2 * 16;
            uint32_t ah[4][4];
            #pragma unroll
            for (int mf = 0; mf < 4; ++mf) {
                int rowm = wm*64 + mf*16 + (lane & 15);
                int colk = k16 + (lane >> 4) * 8;
                ldsm_x4(ah[mf][0], ah[mf][1], ah[mf][2], ah[mf][3],
                        smem_u32(sA + rowm * G1_SA + colk));
            }
            uint32_t bh[2][4];
            #pragma unroll
            for (int p = 0; p < 2; ++p) {
                int krow = k16 + (lane & 15);
                int ncol = wn*32 + p*16 + (lane >> 4) * 8;
                ldsm_x4t(bh[p][0], bh[p][1], bh[p][2], bh[p][3],
                         smem_u32(sB + krow * G1_SB + ncol));
            }
            #pragma unroll
            for (int mf = 0; mf < 4; ++mf) {
                #pragma unroll
                for (int nf = 0; nf < 4; ++nf) {
                    const int p = nf >> 1, hh = (nf & 1) * 2;
                    mma_f16(acc[mf][nf][0], acc[mf][nf][1], acc[mf][nf][2], acc[mf][nf][3],
                            ah[mf][0], ah[mf][1], ah[mf][2], ah[mf][3],
                            bh[p][hh], bh[p][hh+1]);
                }
            }
        }
        __syncthreads();
    }

    // epilogue: q,k -> elu+1; v raw; packed fp16 stores (c always even)
    const int type = m0 >> 8;  // 0=q, 1=k, 2=v
    #pragma unroll
    for (int mf = 0; mf < 4; ++mf) {
        int rbase = m0 + wm*64 + mf*16 + (lane >> 2);
        #pragma unroll
        for (int nf = 0; nf < 4; ++nf) {
            int c = n0 + wn*32 + nf*8 + (lane & 3) * 2;
            #pragma unroll
            for (int rh = 0; rh < 2; ++rh) {
                int r = rbase + rh * 8;
                float v0 = acc[mf][nf][rh*2 + 0];
                float v1 = acc[mf][nf][rh*2 + 1];
                if (type == 0) {
                    g_QKp[(((size_t)b*C_ + r)*N_ + c) >> 1] = packh(elu1(v0), elu1(v1));
                } else if (type == 1) {
                    g_KKp[(((size_t)b*C_ + (r-256))*N_ + c) >> 1] = packh(elu1(v0), elu1(v1));
                } else {
                    g_Vp [(((size_t)b*C_ + (r-512))*N_ + c) >> 1] = packh(v0, v1);
                }
            }
        }
    }
}

// ---------------------------------------------------------------- reduce (packed fp16 in, fp32 acc)
__global__ __launch_bounds__(256) void k_reduce() {
    const int c = blockIdx.x, b = blockIdx.y;
    const uint4* kk = reinterpret_cast<const uint4*>(&g_KKp[((size_t)b*C_ + c) * (N_ / 2)]);
    const uint4* vv = reinterpret_cast<const uint4*>(&g_Vp [((size_t)b*C_ + c) * (N_ / 2)]);
    float skv = 0.f, sk = 0.f;
    for (int i = threadIdx.x; i < 512; i += 256) {
        uint4 K = kk[i], V = vv[i];
        float k0 = lo16(K.x), k1 = hi16(K.x), k2 = lo16(K.y), k3 = hi16(K.y);
        float k4 = lo16(K.z), k5 = hi16(K.z), k6 = lo16(K.w), k7 = hi16(K.w);
        float u0 = lo16(V.x), u1 = hi16(V.x), u2 = lo16(V.y), u3 = hi16(V.y);
        float u4 = lo16(V.z), u5 = hi16(V.z), u6 = lo16(V.w), u7 = hi16(V.w);
        skv = fmaf(k0, u0, skv); skv = fmaf(k1, u1, skv);
        skv = fmaf(k2, u2, skv); skv = fmaf(k3, u3, skv);
        skv = fmaf(k4, u4, skv); skv = fmaf(k5, u5, skv);
        skv = fmaf(k6, u6, skv); skv = fmaf(k7, u7, skv);
        sk += k0 + k1 + k2 + k3 + k4 + k5 + k6 + k7;
    }
    #pragma unroll
    for (int o = 16; o > 0; o >>= 1) {
        skv += __shfl_xor_sync(0xFFFFFFFFu, skv, o);
        sk  += __shfl_xor_sync(0xFFFFFFFFu, sk, o);
    }
    __shared__ float s1[8], s2[8];
    int w = threadIdx.x >> 5, l = threadIdx.x & 31;
    if (l == 0) { s1[w] = skv; s2[w] = sk; }
    __syncthreads();
    if (threadIdx.x == 0) {
        float a = 0.f, d = 0.f;
        #pragma unroll
        for (int i = 0; i < 8; ++i) { a += s1[i]; d += s2[i]; }
        g_s[b * C_ + c] = a / fmaxf(d, 1e-6f);
    }
}

// ---------------------------------------------------------------- GEMM2 + LN
// out[256,4096] = (W_out * diag(s)) @ QK[256,4096] per batch, fused channel LN.
// Block 256(M)x64(N), kstep 16, 256 thr (8 warps: 4M x 2N; warp tile 64x32).
// s folded into A at staging (fp32 w_out * s -> packh); B = pure packed copies.
#define G2_SA 24   // 16 k + 8 pad
#define G2_SB 72   // 64 n + 8 pad

__global__ __launch_bounds__(256) void k_gemm2(const float* __restrict__ w_out,
                                               const float* __restrict__ gamma,
                                               const float* __restrict__ beta,
                                               float* __restrict__ out) {
    __shared__ __half sA[256 * G2_SA];
    __shared__ __half sB[16 * G2_SB];
    __shared__ float s_sm[256], g_sm[256], be_sm[256];
    __shared__ float red_s[32][64];
    __shared__ float red_q[32][64];
    __shared__ float mu_s[64], rs_s[64];

    const int tid = threadIdx.x, lane = tid & 31, wid = tid >> 5;
    const int wm = wid >> 1, wn = wid & 1;
    const int n0 = blockIdx.x * 64, b = blockIdx.y;
    const uint32_t* QKp = g_QKp + (size_t)b * C_ * (N_ / 2);

    s_sm[tid]  = g_s[b * C_ + tid];
    g_sm[tid]  = gamma[tid];
    be_sm[tid] = beta[tid];
    __syncthreads();

    // A stage: 256 rows x 16 k fp32; thread -> row tid (4 float4), scale by s_sm[kt+j]
    // B stage: 16 rows x 64 n packed = 128 uint4; tid<128 -> brow=(tid&127)>>3, bnc=(tid&7)*8
    const int brow = (tid & 127) >> 3, bnc = (tid & 7) * 8;

    float acc[4][4][4];
    #pragma unroll
    for (int i = 0; i < 4; ++i)
        #pragma unroll
        for (int j = 0; j < 4; ++j)
            #pragma unroll
            for (int e = 0; e < 4; ++e) acc[i][j][e] = 0.f;

    float4 a0, a1, a2, a3;
    uint4 bS0;
    {
        const float* wp = w_out + (size_t)tid * 256;
        a0 = *reinterpret_cast<const float4*>(wp + 0);
        a1 = *reinterpret_cast<const float4*>(wp + 4);
        a2 = *reinterpret_cast<const float4*>(wp + 8);
        a3 = *reinterpret_cast<const float4*>(wp + 12);
        if (tid < 128)
            bS0 = *reinterpret_cast<const uint4*>(QKp + (size_t)brow * (N_ / 2) + ((n0 + bnc) >> 1));
    }

    #pragma unroll 1
    for (int t = 0; t < 16; ++t) {
        const int kt = t * 16;
        {
            const int ao = tid * G2_SA;
            *reinterpret_cast<uint4*>(&sA[ao]) =
                make_uint4(packh(a0.x * s_sm[kt+0],  a0.y * s_sm[kt+1]),
                           packh(a0.z * s_sm[kt+2],  a0.w * s_sm[kt+3]),
                           packh(a1.x * s_sm[kt+4],  a1.y * s_sm[kt+5]),
                           packh(a1.z * s_sm[kt+6],  a1.w * s_sm[kt+7]));
            *reinterpret_cast<uint4*>(&sA[ao + 8]) =
                make_uint4(packh(a2.x * s_sm[kt+8],  a2.y * s_sm[kt+9]),
                           packh(a2.z * s_sm[kt+10], a2.w * s_sm[kt+11]),
                           packh(a3.x * s_sm[kt+12], a3.y * s_sm[kt+13]),
                           packh(a3.z * s_sm[kt+14], a3.w * s_sm[kt+15]));
            if (tid < 128)
                *reinterpret_cast<uint4*>(&sB[brow * G2_SB + bnc]) = bS0;
        }
        __syncthreads();
        if (t < 15) {
            int ktn = kt + 16;
            const float* wp = w_out + (size_t)tid * 256 + ktn;
            a0 = *reinterpret_cast<const float4*>(wp + 0);
            a1 = *reinterpret_cast<const float4*>(wp + 4);
            a2 = *reinterpret_cast<const float4*>(wp + 8);
            a3 = *reinterpret_cast<const float4*>(wp + 12);
            if (tid < 128)
                bS0 = *reinterpret_cast<const uint4*>(QKp + (size_t)(ktn + brow) * (N_ / 2) + ((n0 + bnc) >> 1));
        }

        uint32_t ah[4][4];
        #pragma unroll
        for (int mf = 0; mf < 4; ++mf) {
            int rowm = wm*64 + mf*16 + (lane & 15);
            int colk = (lane >> 4) * 8;
            ldsm_x4(ah[mf][0], ah[mf][1], ah[mf][2], ah[mf][3],
                    smem_u32(sA + rowm * G2_SA + colk));
        }
        uint32_t bh[2][4];
        #pragma unroll
        for (int p = 0; p < 2; ++p) {
            int krow = lane & 15;
            int ncol = wn*32 + p*16 + (lane >> 4) * 8;
            ldsm_x4t(bh[p][0], bh[p][1], bh[p][2], bh[p][3],
                     smem_u32(sB + krow * G2_SB + ncol));
        }
        #pragma unroll
        for (int mf = 0; mf < 4; ++mf) {
            #pragma unroll
            for (int nf = 0; nf < 4; ++nf) {
                const int p = nf >> 1, hh = (nf & 1) * 2;
                mma_f16(acc[mf][nf][0], acc[mf][nf][1], acc[mf][nf][2], acc[mf][nf][3],
                        ah[mf][0], ah[mf][1], ah[mf][2], ah[mf][3],
                        bh[p][hh], bh[p][hh+1]);
            }
        }
        __syncthreads();
    }

    // ---- fused LayerNorm over the 256 channels this block owns ----
    #pragma unroll
    for (int nf = 0; nf < 4; ++nf)
        #pragma unroll
        for (int e = 0; e < 2; ++e) {
            float s = 0.f, q = 0.f;
            #pragma unroll
            for (int mf = 0; mf < 4; ++mf)
                #pragma unroll
                for (int rh = 0; rh < 2; ++rh) {
                    float v = acc[mf][nf][rh*2 + e];
                    s += v; q = fmaf(v, v, q);
                }
            int col = wn*32 + nf*8 + (lane & 3)*2 + e;
            red_s[wm*8 + (lane >> 2)][col] = s;
            red_q[wm*8 + (lane >> 2)][col] = q;
        }
    __syncthreads();
    if (tid < 64) {
        float s = 0.f, q = 0.f;
        #pragma unroll
        for (int r = 0; r < 32; ++r) { s += red_s[r][tid]; q += red_q[r][tid]; }
        float mu  = s * (1.f / 256.f);
        float var = q * (1.f / 256.f) - mu * mu;
        mu_s[tid] = mu;
        rs_s[tid] = rsqrtf(var + 1e-5f);
    }
    __syncthreads();

    #pragma unroll
    for (int mf = 0; mf < 4; ++mf) {
        int rbase = wm*64 + mf*16 + (lane >> 2);
        #pragma unroll
        for (int nf = 0; nf < 4; ++nf) {
            int col = wn*32 + nf*8 + (lane & 3)*2;
            #pragma unroll
            for (int rh = 0; rh < 2; ++rh) {
                int r = rbase + rh*8;
                float ga = g_sm[r], be = be_sm[r];
                float v0 = (acc[mf][nf][rh*2+0] - mu_s[col])   * rs_s[col]   * ga + be;
                float v1 = (acc[mf][nf][rh*2+1] - mu_s[col+1]) * rs_s[col+1] * ga + be;
                *reinterpret_cast<float2*>(&out[((size_t)b*C_ + r)*N_ + n0 + col]) =
                    make_float2(v0, v1);
            }
        }
    }
}

// ----------------------------------------------------------------
extern "C" void kernel_launch(void* const* d_in, const int* in_sizes, int n_in,
                              void* d_out, int out_size) {
    const float* x     = (const float*)d_in[0];
    const float* w_qkv = (const float*)d_in[1];
    const float* w_out = (const float*)d_in[2];
    const float* gamma = (const float*)d_in[3];
    const float* beta  = (const float*)d_in[4];
    float* out = (float*)d_out;

    k_gemm1 <<<dim3(32, 6, 16), 256>>>(x, w_qkv);
    k_reduce<<<dim3(256, 16),   256>>>();
    k_gemm2 <<<dim3(64, 16),    256>>>(w_out, gamma, beta, out);
}

// round 16
// speedup vs baseline: 2.2348x; 1.0253x over previous
#include <cuda_runtime.h>
#include <cuda_fp16.h>
#include <math.h>
#include <stdint.h>

// Shapes: x [16,256,4096], w_qkv [768,256], w_out [256,256], gamma/beta [256]
#define C_ 256
#define N_ 4096

// scratch: packed fp16x2 intermediates in plain uint32 arrays + fp32 s.
// EXACTLY 3 kernel launches (hard constraint, rounds 1-15).
__device__ uint32_t g_QKp[8388608];   // elu(q)+1 packed fp16x2
__device__ uint32_t g_KKp[8388608];   // elu(k)+1 packed
__device__ uint32_t g_Vp [8388608];   // v packed
__device__ float    g_s  [4096];      // per (b,c) scale

// ---------------------------------------------------------------- helpers
__device__ __forceinline__ uint32_t smem_u32(const void* p) {
    return (uint32_t)__cvta_generic_to_shared(p);
}
__device__ __forceinline__ void ldsm_x4(uint32_t& r0, uint32_t& r1, uint32_t& r2, uint32_t& r3, uint32_t a) {
    asm volatile("ldmatrix.sync.aligned.m8n8.x4.shared.b16 {%0,%1,%2,%3}, [%4];"
                 : "=r"(r0), "=r"(r1), "=r"(r2), "=r"(r3) : "r"(a));
}
__device__ __forceinline__ void ldsm_x4t(uint32_t& r0, uint32_t& r1, uint32_t& r2, uint32_t& r3, uint32_t a) {
    asm volatile("ldmatrix.sync.aligned.m8n8.x4.trans.shared.b16 {%0,%1,%2,%3}, [%4];"
                 : "=r"(r0), "=r"(r1), "=r"(r2), "=r"(r3) : "r"(a));
}
__device__ __forceinline__ void mma_f16(float& d0, float& d1, float& d2, float& d3,
                                        uint32_t a0, uint32_t a1, uint32_t a2, uint32_t a3,
                                        uint32_t b0, uint32_t b1) {
    asm volatile("mma.sync.aligned.m16n8k16.row.col.f32.f16.f16.f32 "
                 "{%0,%1,%2,%3},{%4,%5,%6,%7},{%8,%9},{%0,%1,%2,%3};"
                 : "+f"(d0), "+f"(d1), "+f"(d2), "+f"(d3)
                 : "r"(a0), "r"(a1), "r"(a2), "r"(a3), "r"(b0), "r"(b1));
}
__device__ __forceinline__ float elu1(float v) { return v > 0.f ? v + 1.f : expf(v); }

// pack (a -> lo, b -> hi) into one fp16x2 word with a single cvt instruction.
// PTX: cvt.rn.f16x2.f32 d, hi_src, lo_src
__device__ __forceinline__ uint32_t packh(float a, float b) {
    uint32_t r;
    asm("cvt.rn.f16x2.f32 %0, %1, %2;" : "=r"(r) : "f"(b), "f"(a));
    return r;
}
__device__ __forceinline__ float lo16(uint32_t w) {
    return __half2float(__ushort_as_half((unsigned short)(w & 0xFFFFu)));
}
__device__ __forceinline__ float hi16(uint32_t w) {
    return __half2float(__ushort_as_half((unsigned short)(w >> 16)));
}

// ---------------------------------------------------------------- GEMM1
// C[768,4096] = W[768,256] @ X[256,4096] per batch, fp16 tensor cores.
// Block 128(M)x128(N), kstep 32, 256 thr (8 warps: 2M x 4N; warp tile 64x32).
// fp32 inputs, cvt-pack at staging; DOUBLE-BUFFERED smem, 1 sync/iter.
#define G1_SA 40    // 32 k + 8 pad
#define G1_SB 136   // 128 n + 8 pad

__global__ __launch_bounds__(256) void k_gemm1(const float* __restrict__ x,
                                               const float* __restrict__ w) {
    __shared__ __half sA[2 * 128 * G1_SA];
    __shared__ __half sB[2 * 32 * G1_SB];

    const int tid = threadIdx.x, lane = tid & 31, wid = tid >> 5;
    const int wm = wid >> 2, wn = wid & 3;
    const int n0 = blockIdx.x * 128, m0 = blockIdx.y * 128, b = blockIdx.z;
    const float* X = x + (size_t)b * C_ * N_;

    const int arow = tid & 127, akc = (tid >> 7) * 16;
    const int brow = tid >> 3, bnc = (tid & 7) * 16;

    float acc[4][4][4];
    #pragma unroll
    for (int i = 0; i < 4; ++i)
        #pragma unroll
        for (int j = 0; j < 4; ++j)
            #pragma unroll
            for (int e = 0; e < 4; ++e) acc[i][j][e] = 0.f;

    float4 a0, a1, a2, a3, b0, b1, b2, b3;
    {
        const float* wp = w + (size_t)(m0 + arow) * 256 + akc;
        a0 = *reinterpret_cast<const float4*>(wp + 0);
        a1 = *reinterpret_cast<const float4*>(wp + 4);
        a2 = *reinterpret_cast<const float4*>(wp + 8);
        a3 = *reinterpret_cast<const float4*>(wp + 12);
        const float* xp = X + (size_t)brow * N_ + n0 + bnc;
        b0 = *reinterpret_cast<const float4*>(xp + 0);
        b1 = *reinterpret_cast<const float4*>(xp + 4);
        b2 = *reinterpret_cast<const float4*>(xp + 8);
        b3 = *reinterpret_cast<const float4*>(xp + 12);
    }
    // prologue: stage 0
    {
        const int ao = arow * G1_SA + akc;
        *reinterpret_cast<uint4*>(&sA[ao]) =
            make_uint4(packh(a0.x, a0.y), packh(a0.z, a0.w),
                       packh(a1.x, a1.y), packh(a1.z, a1.w));
        *reinterpret_cast<uint4*>(&sA[ao + 8]) =
            make_uint4(packh(a2.x, a2.y), packh(a2.z, a2.w),
                       packh(a3.x, a3.y), packh(a3.z, a3.w));
        const int bo = brow * G1_SB + bnc;
        *reinterpret_cast<uint4*>(&sB[bo]) =
            make_uint4(packh(b0.x, b0.y), packh(b0.z, b0.w),
                       packh(b1.x, b1.y), packh(b1.z, b1.w));
        *reinterpret_cast<uint4*>(&sB[bo + 8]) =
            make_uint4(packh(b2.x, b2.y), packh(b2.z, b2.w),
                       packh(b3.x, b3.y), packh(b3.z, b3.w));
    }
    __syncthreads();

    #pragma unroll 1
    for (int t = 0; t < 8; ++t) {
        const int cur = t & 1;
        if (t < 7) {
            int kt = (t + 1) * 32;
            const float* wp = w + (size_t)(m0 + arow) * 256 + kt + akc;
            a0 = *reinterpret_cast<const float4*>(wp + 0);
            a1 = *reinterpret_cast<const float4*>(wp + 4);
            a2 = *reinterpret_cast<const float4*>(wp + 8);
            a3 = *reinterpret_cast<const float4*>(wp + 12);
            const float* xp = X + (size_t)(kt + brow) * N_ + n0 + bnc;
            b0 = *reinterpret_cast<const float4*>(xp + 0);
            b1 = *reinterpret_cast<const float4*>(xp + 4);
            b2 = *reinterpret_cast<const float4*>(xp + 8);
            b3 = *reinterpret_cast<const float4*>(xp + 12);
        }

        // compute current stage
        const __half* cA = sA + cur * 128 * G1_SA;
        const __half* cB = sB + cur * 32 * G1_SB;
        #pragma unroll
        for (int k2 = 0; k2 < 2; ++k2) {
            const int k16 = k2 * 16;
            uint32_t ah[4][4];
            #pragma unroll
            for (int mf = 0; mf < 4; ++mf) {
                int rowm = wm*64 + mf*16 + (lane & 15);
                int colk = k16 + (lane >> 4) * 8;
                ldsm_x4(ah[mf][0], ah[mf][1], ah[mf][2], ah[mf][3],
                        smem_u32(cA + rowm * G1_SA + colk));
            }
            uint32_t bh[2][4];
            #pragma unroll
            for (int p = 0; p < 2; ++p) {
                int krow = k16 + (lane & 15);
                int ncol = wn*32 + p*16 + (lane >> 4) * 8;
                ldsm_x4t(bh[p][0], bh[p][1], bh[p][2], bh[p][3],
                         smem_u32(cB + krow * G1_SB + ncol));
            }
            #pragma unroll
            for (int mf = 0; mf < 4; ++mf) {
                #pragma unroll
                for (int nf = 0; nf < 4; ++nf) {
                    const int p = nf >> 1, hh = (nf & 1) * 2;
                    mma_f16(acc[mf][nf][0], acc[mf][nf][1], acc[mf][nf][2], acc[mf][nf][3],
                            ah[mf][0], ah[mf][1], ah[mf][2], ah[mf][3],
                            bh[p][hh], bh[p][hh+1]);
                }
            }
        }

        // stage next into the other buffer
        if (t < 7) {
            const int nx = (t + 1) & 1;
            __half* nA = sA + nx * 128 * G1_SA;
            __half* nB = sB + nx * 32 * G1_SB;
            const int ao = arow * G1_SA + akc;
            *reinterpret_cast<uint4*>(&nA[ao]) =
                make_uint4(packh(a0.x, a0.y), packh(a0.z, a0.w),
                           packh(a1.x, a1.y), packh(a1.z, a1.w));
            *reinterpret_cast<uint4*>(&nA[ao + 8]) =
                make_uint4(packh(a2.x, a2.y), packh(a2.z, a2.w),
                           packh(a3.x, a3.y), packh(a3.z, a3.w));
            const int bo = brow * G1_SB + bnc;
            *reinterpret_cast<uint4*>(&nB[bo]) =
                make_uint4(packh(b0.x, b0.y), packh(b0.z, b0.w),
                           packh(b1.x, b1.y), packh(b1.z, b1.w));
            *reinterpret_cast<uint4*>(&nB[bo + 8]) =
                make_uint4(packh(b2.x, b2.y), packh(b2.z, b2.w),
                           packh(b3.x, b3.y), packh(b3.z, b3.w));
        }
        __syncthreads();
    }

    // epilogue: q,k -> elu+1; v raw; packed fp16 stores (c always even)
    const int type = m0 >> 8;  // 0=q, 1=k, 2=v
    #pragma unroll
    for (int mf = 0; mf < 4; ++mf) {
        int rbase = m0 + wm*64 + mf*16 + (lane >> 2);
        #pragma unroll
        for (int nf = 0; nf < 4; ++nf) {
            int c = n0 + wn*32 + nf*8 + (lane & 3) * 2;
            #pragma unroll
            for (int rh = 0; rh < 2; ++rh) {
                int r = rbase + rh * 8;
                float v0 = acc[mf][nf][rh*2 + 0];
                float v1 = acc[mf][nf][rh*2 + 1];
                if (type == 0) {
                    g_QKp[(((size_t)b*C_ + r)*N_ + c) >> 1] = packh(elu1(v0), elu1(v1));
                } else if (type == 1) {
                    g_KKp[(((size_t)b*C_ + (r-256))*N_ + c) >> 1] = packh(elu1(v0), elu1(v1));
                } else {
                    g_Vp [(((size_t)b*C_ + (r-512))*N_ + c) >> 1] = packh(v0, v1);
                }
            }
        }
    }
}

// ---------------------------------------------------------------- reduce (packed fp16 in, fp32 acc)
__global__ __launch_bounds__(256) void k_reduce() {
    const int c = blockIdx.x, b = blockIdx.y;
    const uint4* kk = reinterpret_cast<const uint4*>(&g_KKp[((size_t)b*C_ + c) * (N_ / 2)]);
    const uint4* vv = reinterpret_cast<const uint4*>(&g_Vp [((size_t)b*C_ + c) * (N_ / 2)]);
    float skv = 0.f, sk = 0.f;
    for (int i = threadIdx.x; i < 512; i += 256) {
        uint4 K = kk[i], V = vv[i];
        float k0 = lo16(K.x), k1 = hi16(K.x), k2 = lo16(K.y), k3 = hi16(K.y);
        float k4 = lo16(K.z), k5 = hi16(K.z), k6 = lo16(K.w), k7 = hi16(K.w);
        float u0 = lo16(V.x), u1 = hi16(V.x), u2 = lo16(V.y), u3 = hi16(V.y);
        float u4 = lo16(V.z), u5 = hi16(V.z), u6 = lo16(V.w), u7 = hi16(V.w);
        skv = fmaf(k0, u0, skv); skv = fmaf(k1, u1, skv);
        skv = fmaf(k2, u2, skv); skv = fmaf(k3, u3, skv);
        skv = fmaf(k4, u4, skv); skv = fmaf(k5, u5, skv);
        skv = fmaf(k6, u6, skv); skv = fmaf(k7, u7, skv);
        sk += k0 + k1 + k2 + k3 + k4 + k5 + k6 + k7;
    }
    #pragma unroll
    for (int o = 16; o > 0; o >>= 1) {
        skv += __shfl_xor_sync(0xFFFFFFFFu, skv, o);
        sk  += __shfl_xor_sync(0xFFFFFFFFu, sk, o);
    }
    __shared__ float s1[8], s2[8];
    int w = threadIdx.x >> 5, l = threadIdx.x & 31;
    if (l == 0) { s1[w] = skv; s2[w] = sk; }
    __syncthreads();
    if (threadIdx.x == 0) {
        float a = 0.f, d = 0.f;
        #pragma unroll
        for (int i = 0; i < 8; ++i) { a += s1[i]; d += s2[i]; }
        g_s[b * C_ + c] = a / fmaxf(d, 1e-6f);
    }
}

// ---------------------------------------------------------------- GEMM2 + LN
// out[256,4096] = (W_out * diag(s)) @ QK[256,4096] per batch, fused channel LN.
// Block 256(M)x64(N), kstep 32, 256 thr (8 warps: 4M x 2N; warp tile 64x32).
// s folded into A at staging (fp32 w_out * s -> cvt-pack); B = pure packed copies.
#define G2_SA 40   // 32 k + 8 pad
#define G2_SB 72   // 64 n + 8 pad

__global__ __launch_bounds__(256) void k_gemm2(const float* __restrict__ w_out,
                                               const float* __restrict__ gamma,
                                               const float* __restrict__ beta,
                                               float* __restrict__ out) {
    __shared__ __half sA[256 * G2_SA];
    __shared__ __half sB[32 * G2_SB];
    __shared__ float s_sm[256], g_sm[256], be_sm[256];
    __shared__ float red_s[32][64];
    __shared__ float red_q[32][64];
    __shared__ float mu_s[64], rs_s[64];

    const int tid = threadIdx.x, lane = tid & 31, wid = tid >> 5;
    const int wm = wid >> 1, wn = wid & 1;
    const int n0 = blockIdx.x * 64, b = blockIdx.y;
    const uint32_t* QKp = g_QKp + (size_t)b * C_ * (N_ / 2);

    s_sm[tid]  = g_s[b * C_ + tid];
    g_sm[tid]  = gamma[tid];
    be_sm[tid] = beta[tid];
    __syncthreads();

    // A stage: 256 rows x 32 k fp32; thread -> row tid (8 float4), scaled by s
    // B stage: 32 rows x 64 n packed = 256 uint4; thread -> brow=tid>>3, bnc=(tid&7)*8
    const int brow = tid >> 3, bnc = (tid & 7) * 8;

    float acc[4][4][4];
    #pragma unroll
    for (int i = 0; i < 4; ++i)
        #pragma unroll
        for (int j = 0; j < 4; ++j)
            #pragma unroll
            for (int e = 0; e < 4; ++e) acc[i][j][e] = 0.f;

    float4 a0, a1, a2, a3, a4, a5, a6, a7;
    uint4 bS0;
    {
        const float* wp = w_out + (size_t)tid * 256;
        a0 = *reinterpret_cast<const float4*>(wp + 0);
        a1 = *reinterpret_cast<const float4*>(wp + 4);
        a2 = *reinterpret_cast<const float4*>(wp + 8);
        a3 = *reinterpret_cast<const float4*>(wp + 12);
        a4 = *reinterpret_cast<const float4*>(wp + 16);
        a5 = *reinterpret_cast<const float4*>(wp + 20);
        a6 = *reinterpret_cast<const float4*>(wp + 24);
        a7 = *reinterpret_cast<const float4*>(wp + 28);
        bS0 = *reinterpret_cast<const uint4*>(QKp + (size_t)brow * (N_ / 2) + ((n0 + bnc) >> 1));
    }

    #pragma unroll 1
    for (int t = 0; t < 8; ++t) {
        const int kt = t * 32;
        {
            const int ao = tid * G2_SA;
            *reinterpret_cast<uint4*>(&sA[ao]) =
                make_uint4(packh(a0.x * s_sm[kt+0],  a0.y * s_sm[kt+1]),
                           packh(a0.z * s_sm[kt+2],  a0.w * s_sm[kt+3]),
                           packh(a1.x * s_sm[kt+4],  a1.y * s_sm[kt+5]),
                           packh(a1.z * s_sm[kt+6],  a1.w * s_sm[kt+7]));
            *reinterpret_cast<uint4*>(&sA[ao + 8]) =
                make_uint4(packh(a2.x * s_sm[kt+8],  a2.y * s_sm[kt+9]),
                           packh(a2.z * s_sm[kt+10], a2.w * s_sm[kt+11]),
                           packh(a3.x * s_sm[kt+12], a3.y * s_sm[kt+13]),
                           packh(a3.z * s_sm[kt+14], a3.w * s_sm[kt+15]));
            *reinterpret_cast<uint4*>(&sA[ao + 16]) =
                make_uint4(packh(a4.x * s_sm[kt+16], a4.y * s_sm[kt+17]),
                           packh(a4.z * s_sm[kt+18], a4.w * s_sm[kt+19]),
                           packh(a5.x * s_sm[kt+20], a5.y * s_sm[kt+21]),
                           packh(a5.z * s_sm[kt+22], a5.w * s_sm[kt+23]));
            *reinterpret_cast<uint4*>(&sA[ao + 24]) =
                make_uint4(packh(a6.x * s_sm[kt+24], a6.y * s_sm[kt+25]),
                           packh(a6.z * s_sm[kt+26], a6.w * s_sm[kt+27]),
                           packh(a7.x * s_sm[kt+28], a7.y * s_sm[kt+29]),
                           packh(a7.z * s_sm[kt+30], a7.w * s_sm[kt+31]));
            *reinterpret_cast<uint4*>(&sB[brow * G2_SB + bnc]) = bS0;
        }
        __syncthreads();
        if (t < 7) {
            int ktn = kt + 32;
            const float* wp = w_out + (size_t)tid * 256 + ktn;
            a0 = *reinterpret_cast<const float4*>(wp + 0);
            a1 = *reinterpret_cast<const float4*>(wp + 4);
            a2 = *reinterpret_cast<const float4*>(wp + 8);
            a3 = *reinterpret_cast<const float4*>(wp + 12);
            a4 = *reinterpret_cast<const float4*>(wp + 16);
            a5 = *reinterpret_cast<const float4*>(wp + 20);
            a6 = *reinterpret_cast<const float4*>(wp + 24);
            a7 = *reinterpret_cast<const float4*>(wp + 28);
            bS0 = *reinterpret_cast<const uint4*>(QKp + (size_t)(ktn + brow) * (N_ / 2) + ((n0 + bnc) >> 1));
        }

        #pragma unroll
        for (int k2 = 0; k2 < 2; ++k2) {
            const int k16 = k2 * 16;
            uint32_t ah[4][4];
            #pragma unroll
            for (int mf = 0; mf < 4; ++mf) {
                int rowm = wm*64 + mf*16 + (lane & 15);
                int colk = k16 + (lane >> 4) * 8;
                ldsm_x4(ah[mf][0], ah[mf][1], ah[mf][2], ah[mf][3],
                        smem_u32(sA + rowm * G2_SA + colk));
            }
            uint32_t bh[2][4];
            #pragma unroll
            for (int p = 0; p < 2; ++p) {
                int krow = k16 + (lane & 15);
                int ncol = wn*32 + p*16 + (lane >> 4) * 8;
                ldsm_x4t(bh[p][0], bh[p][1], bh[p][2], bh[p][3],
                         smem_u32(sB + krow * G2_SB + ncol));
            }
            #pragma unroll
            for (int mf = 0; mf < 4; ++mf) {
                #pragma unroll
                for (int nf = 0; nf < 4; ++nf) {
                    const int p = nf >> 1, hh = (nf & 1) * 2;
                    mma_f16(acc[mf][nf][0], acc[mf][nf][1], acc[mf][nf][2], acc[mf][nf][3],
                            ah[mf][0], ah[mf][1], ah[mf][2], ah[mf][3],
                            bh[p][hh], bh[p][hh+1]);
                }
            }
        }
        __syncthreads();
    }

    // ---- fused LayerNorm over the 256 channels this block owns ----
    #pragma unroll
    for (int nf = 0; nf < 4; ++nf)
        #pragma unroll
        for (int e = 0; e < 2; ++e) {
            float s = 0.f, q = 0.f;
            #pragma unroll
            for (int mf = 0; mf < 4; ++mf)
                #pragma unroll
                for (int rh = 0; rh < 2; ++rh) {
                    float v = acc[mf][nf][rh*2 + e];
                    s += v; q = fmaf(v, v, q);
                }
            int col = wn*32 + nf*8 + (lane & 3)*2 + e;
            red_s[wm*8 + (lane >> 2)][col] = s;
            red_q[wm*8 + (lane >> 2)][col] = q;
        }
    __syncthreads();
    if (tid < 64) {
        float s = 0.f, q = 0.f;
        #pragma unroll
        for (int r = 0; r < 32; ++r) { s += red_s[r][tid]; q += red_q[r][tid]; }
        float mu  = s * (1.f / 256.f);
        float var = q * (1.f / 256.f) - mu * mu;
        mu_s[tid] = mu;
        rs_s[tid] = rsqrtf(var + 1e-5f);
    }
    __syncthreads();

    #pragma unroll
    for (int mf = 0; mf < 4; ++mf) {
        int rbase = wm*64 + mf*16 + (lane >> 2);
        #pragma unroll
        for (int nf = 0; nf < 4; ++nf) {
            int col = wn*32 + nf*8 + (lane & 3)*2;
            #pragma unroll
            for (int rh = 0; rh < 2; ++rh) {
                int r = rbase + rh*8;
                float ga = g_sm[r], be = be_sm[r];
                float v0 = (acc[mf][nf][rh*2+0] - mu_s[col])   * rs_s[col]   * ga + be;
                float v1 = (acc[mf][nf][rh*2+1] - mu_s[col+1]) * rs_s[col+1] * ga + be;
                *reinterpret_cast<float2*>(&out[((size_t)b*C_ + r)*N_ + n0 + col]) =
                    make_float2(v0, v1);
            }
        }
    }
}

// ----------------------------------------------------------------
extern "C" void kernel_launch(void* const* d_in, const int* in_sizes, int n_in,
                              void* d_out, int out_size) {
    const float* x     = (const float*)d_in[0];
    const float* w_qkv = (const float*)d_in[1];
    const float* w_out = (const float*)d_in[2];
    const float* gamma = (const float*)d_in[3];
    const float* beta  = (const float*)d_in[4];
    float* out = (float*)d_out;

    k_gemm1 <<<dim3(32, 6, 16), 256>>>(x, w_qkv);
    k_reduce<<<dim3(256, 16),   256>>>();
    k_gemm2 <<<dim3(64, 16),    256>>>(w_out, gamma, beta, out);
}

// round 17
// speedup vs baseline: 2.3775x; 1.0639x over previous
#include <cuda_runtime.h>
#include <cuda_fp16.h>
#include <math.h>
#include <stdint.h>

// Shapes: x [16,256,4096], w_qkv [768,256], w_out [256,256], gamma/beta [256]
#define C_ 256
#define N_ 4096

// scratch. EXACTLY 3 kernel launches (hard constraint, rounds 1-16).
__device__ uint32_t g_QKp[8388608];   // elu(q)+1 packed fp16x2
__device__ float    g_pkv[131072];    // [b][nblk=32][c=256] partial sum kk*v
__device__ float    g_pdk[131072];    // [b][nblk][c] partial sum kk
__device__ float    g_s  [4096];      // per (b,c) scale

// ---------------------------------------------------------------- helpers
__device__ __forceinline__ uint32_t smem_u32(const void* p) {
    return (uint32_t)__cvta_generic_to_shared(p);
}
__device__ __forceinline__ void ldsm_x4(uint32_t& r0, uint32_t& r1, uint32_t& r2, uint32_t& r3, uint32_t a) {
    asm volatile("ldmatrix.sync.aligned.m8n8.x4.shared.b16 {%0,%1,%2,%3}, [%4];"
                 : "=r"(r0), "=r"(r1), "=r"(r2), "=r"(r3) : "r"(a));
}
__device__ __forceinline__ void ldsm_x4t(uint32_t& r0, uint32_t& r1, uint32_t& r2, uint32_t& r3, uint32_t a) {
    asm volatile("ldmatrix.sync.aligned.m8n8.x4.trans.shared.b16 {%0,%1,%2,%3}, [%4];"
                 : "=r"(r0), "=r"(r1), "=r"(r2), "=r"(r3) : "r"(a));
}
__device__ __forceinline__ void mma_f16(float& d0, float& d1, float& d2, float& d3,
                                        uint32_t a0, uint32_t a1, uint32_t a2, uint32_t a3,
                                        uint32_t b0, uint32_t b1) {
    asm volatile("mma.sync.aligned.m16n8k16.row.col.f32.f16.f16.f32 "
                 "{%0,%1,%2,%3},{%4,%5,%6,%7},{%8,%9},{%0,%1,%2,%3};"
                 : "+f"(d0), "+f"(d1), "+f"(d2), "+f"(d3)
                 : "r"(a0), "r"(a1), "r"(a2), "r"(a3), "r"(b0), "r"(b1));
}
__device__ __forceinline__ float elu1(float v) { return v > 0.f ? v + 1.f : expf(v); }

// pack (a -> lo, b -> hi) into one fp16x2 word with a single cvt instruction.
__device__ __forceinline__ uint32_t packh(float a, float b) {
    uint32_t r;
    asm("cvt.rn.f16x2.f32 %0, %1, %2;" : "=r"(r) : "f"(b), "f"(a));
    return r;
}
__device__ __forceinline__ float lo16(uint32_t w) {
    return __half2float(__ushort_as_half((unsigned short)(w & 0xFFFFu)));
}
__device__ __forceinline__ float hi16(uint32_t w) {
    return __half2float(__ushort_as_half((unsigned short)(w >> 16)));
}

// ---------------------------------------------------------------- GEMM1 (+fused kv partials)
// Per batch: C = W[768,256] @ X[256,4096]. Block 128(M)x128(N), kstep 32,
// 256 thr (8 warps: 2M x 4N; warp tile 64x32), single-buffered smem.
// ytile 0,1: q rows (0-255) -> QKp.  ytile 2..5: mixed tile of 64 K rows
// (256+i*64..) and 64 V rows (512+i*64..): epilogue computes per-channel
// partial sums of kk and kk*v over this block's 128 columns.
#define G1_SA 40    // 32 k + 8 pad
#define G1_SB 136   // 128 n + 8 pad

__global__ __launch_bounds__(256) void k_gemm1(const float* __restrict__ x,
                                               const float* __restrict__ w) {
    __shared__ __half sA[128 * G1_SA];
    __shared__ __half sB[32 * G1_SB];
    __shared__ uint32_t skk[64 * 68];     // packed fp16 kk tile [64 rows][64 packed cols]
    __shared__ float sdk[64 * 4];         // per-row kk sums, per wn
    __shared__ float skv[64 * 4];         // per-row kk*v sums, per wn

    const int tid = threadIdx.x, lane = tid & 31, wid = tid >> 5;
    const int wm = wid >> 2, wn = wid & 3;
    const int ytile = blockIdx.y;
    const int n0 = blockIdx.x * 128, b = blockIdx.z;
    const float* X = x + (size_t)b * C_ * N_;

    const int arow = tid & 127, akc = (tid >> 7) * 16;
    const int brow = tid >> 3, bnc = (tid & 7) * 16;

    // source W row for this thread's A staging (q tiles vs mixed K/V tiles)
    int srcrow;
    if (ytile < 2) srcrow = ytile * 128 + arow;
    else srcrow = (arow < 64) ? (256 + (ytile - 2) * 64 + arow)
                              : (448 + (ytile - 2) * 64 + arow);
    const float* wrow = w + (size_t)srcrow * 256;

    float acc[4][4][4];
    #pragma unroll
    for (int i = 0; i < 4; ++i)
        #pragma unroll
        for (int j = 0; j < 4; ++j)
            #pragma unroll
            for (int e = 0; e < 4; ++e) acc[i][j][e] = 0.f;

    float4 a0, a1, a2, a3, b0, b1, b2, b3;
    {
        a0 = *reinterpret_cast<const float4*>(wrow + akc + 0);
        a1 = *reinterpret_cast<const float4*>(wrow + akc + 4);
        a2 = *reinterpret_cast<const float4*>(wrow + akc + 8);
        a3 = *reinterpret_cast<const float4*>(wrow + akc + 12);
        const float* xp = X + (size_t)brow * N_ + n0 + bnc;
        b0 = *reinterpret_cast<const float4*>(xp + 0);
        b1 = *reinterpret_cast<const float4*>(xp + 4);
        b2 = *reinterpret_cast<const float4*>(xp + 8);
        b3 = *reinterpret_cast<const float4*>(xp + 12);
    }

    #pragma unroll 1
    for (int t = 0; t < 8; ++t) {
        {
            const int ao = arow * G1_SA + akc;
            *reinterpret_cast<uint4*>(&sA[ao]) =
                make_uint4(packh(a0.x, a0.y), packh(a0.z, a0.w),
                           packh(a1.x, a1.y), packh(a1.z, a1.w));
            *reinterpret_cast<uint4*>(&sA[ao + 8]) =
                make_uint4(packh(a2.x, a2.y), packh(a2.z, a2.w),
                           packh(a3.x, a3.y), packh(a3.z, a3.w));
            const int bo = brow * G1_SB + bnc;
            *reinterpret_cast<uint4*>(&sB[bo]) =
                make_uint4(packh(b0.x, b0.y), packh(b0.z, b0.w),
                           packh(b1.x, b1.y), packh(b1.z, b1.w));
            *reinterpret_cast<uint4*>(&sB[bo + 8]) =
                make_uint4(packh(b2.x, b2.y), packh(b2.z, b2.w),
                           packh(b3.x, b3.y), packh(b3.z, b3.w));
        }
        __syncthreads();
        if (t < 7) {
            int kt = (t + 1) * 32;
            a0 = *reinterpret_cast<const float4*>(wrow + kt + akc + 0);
            a1 = *reinterpret_cast<const float4*>(wrow + kt + akc + 4);
            a2 = *reinterpret_cast<const float4*>(wrow + kt + akc + 8);
            a3 = *reinterpret_cast<const float4*>(wrow + kt + akc + 12);
            const float* xp = X + (size_t)(kt + brow) * N_ + n0 + bnc;
            b0 = *reinterpret_cast<const float4*>(xp + 0);
            b1 = *reinterpret_cast<const float4*>(xp + 4);
            b2 = *reinterpret_cast<const float4*>(xp + 8);
            b3 = *reinterpret_cast<const float4*>(xp + 12);
        }

        #pragma unroll
        for (int k2 = 0; k2 < 2; ++k2) {
            const int k16 = k2 * 16;
            uint32_t ah[4][4];
            #pragma unroll
            for (int mf = 0; mf < 4; ++mf) {
                int rowm = wm*64 + mf*16 + (lane & 15);
                int colk = k16 + (lane >> 4) * 8;
                ldsm_x4(ah[mf][0], ah[mf][1], ah[mf][2], ah[mf][3],
                        smem_u32(sA + rowm * G1_SA + colk));
            }
            uint32_t bh[2][4];
            #pragma unroll
            for (int p = 0; p < 2; ++p) {
                int krow = k16 + (lane & 15);
                int ncol = wn*32 + p*16 + (lane >> 4) * 8;
                ldsm_x4t(bh[p][0], bh[p][1], bh[p][2], bh[p][3],
                         smem_u32(sB + krow * G1_SB + ncol));
            }
            #pragma unroll
            for (int mf = 0; mf < 4; ++mf) {
                #pragma unroll
                for (int nf = 0; nf < 4; ++nf) {
                    const int p = nf >> 1, hh = (nf & 1) * 2;
                    mma_f16(acc[mf][nf][0], acc[mf][nf][1], acc[mf][nf][2], acc[mf][nf][3],
                            ah[mf][0], ah[mf][1], ah[mf][2], ah[mf][3],
                            bh[p][hh], bh[p][hh+1]);
                }
            }
        }
        __syncthreads();
    }

    if (ytile < 2) {
        // q epilogue: elu+1, packed fp16 stores
        #pragma unroll
        for (int mf = 0; mf < 4; ++mf) {
            int rbase = ytile*128 + wm*64 + mf*16 + (lane >> 2);
            #pragma unroll
            for (int nf = 0; nf < 4; ++nf) {
                int c = n0 + wn*32 + nf*8 + (lane & 3) * 2;
                #pragma unroll
                for (int rh = 0; rh < 2; ++rh) {
                    int r = rbase + rh * 8;
                    g_QKp[(((size_t)b*C_ + r)*N_ + c) >> 1] =
                        packh(elu1(acc[mf][nf][rh*2 + 0]), elu1(acc[mf][nf][rh*2 + 1]));
                }
            }
        }
    } else {
        // kv epilogue: wm=0 warps own K rows (rel 0..63), wm=1 own V rows (rel 0..63)
        if (wm == 0) {
            #pragma unroll
            for (int mf = 0; mf < 4; ++mf) {
                #pragma unroll
                for (int rh = 0; rh < 2; ++rh) {
                    int rv = mf*16 + (lane >> 2) + rh*8;
                    float rsum = 0.f;
                    #pragma unroll
                    for (int nf = 0; nf < 4; ++nf) {
                        uint32_t pk = packh(elu1(acc[mf][nf][rh*2+0]),
                                            elu1(acc[mf][nf][rh*2+1]));
                        rsum += lo16(pk) + hi16(pk);
                        skk[rv * 68 + wn*16 + nf*4 + (lane & 3)] = pk;
                    }
                    rsum += __shfl_xor_sync(0xFFFFFFFFu, rsum, 1);
                    rsum += __shfl_xor_sync(0xFFFFFFFFu, rsum, 2);
                    if ((lane & 3) == 0) sdk[rv*4 + wn] = rsum;
                }
            }
        }
        __syncthreads();
        if (wm == 1) {
            #pragma unroll
            for (int mf = 0; mf < 4; ++mf) {
                #pragma unroll
                for (int rh = 0; rh < 2; ++rh) {
                    int rv = mf*16 + (lane >> 2) + rh*8;
                    float psum = 0.f;
                    #pragma unroll
                    for (int nf = 0; nf < 4; ++nf) {
                        uint32_t pk = skk[rv * 68 + wn*16 + nf*4 + (lane & 3)];
                        psum = fmaf(lo16(pk), acc[mf][nf][rh*2+0], psum);
                        psum = fmaf(hi16(pk), acc[mf][nf][rh*2+1], psum);
                    }
                    psum += __shfl_xor_sync(0xFFFFFFFFu, psum, 1);
                    psum += __shfl_xor_sync(0xFFFFFFFFu, psum, 2);
                    if ((lane & 3) == 0) skv[rv*4 + wn] = psum;
                }
            }
        }
        __syncthreads();
        if (tid < 64) {
            int c = (ytile - 2) * 64 + tid;
            float kv = skv[tid*4+0] + skv[tid*4+1] + skv[tid*4+2] + skv[tid*4+3];
            float dk = sdk[tid*4+0] + sdk[tid*4+1] + sdk[tid*4+2] + sdk[tid*4+3];
            size_t idx = ((size_t)b * 32 + blockIdx.x) * 256 + c;
            g_pkv[idx] = kv;
            g_pdk[idx] = dk;
        }
    }
}

// ---------------------------------------------------------------- scale: s = sum(kv)/max(sum(dk),1e-6)
__global__ __launch_bounds__(256) void k_scale() {
    const int b = blockIdx.x, c = threadIdx.x;
    float kv = 0.f, dk = 0.f;
    #pragma unroll
    for (int j = 0; j < 32; ++j) {
        kv += g_pkv[((size_t)b * 32 + j) * 256 + c];
        dk += g_pdk[((size_t)b * 32 + j) * 256 + c];
    }
    g_s[b * 256 + c] = kv / fmaxf(dk, 1e-6f);
}

// ---------------------------------------------------------------- GEMM2 + LN (verbatim round 16)
// out[256,4096] = (W_out * diag(s)) @ QK[256,4096] per batch, fused channel LN.
// Block 256(M)x64(N), kstep 32, 256 thr (8 warps: 4M x 2N; warp tile 64x32).
#define G2_SA 40   // 32 k + 8 pad
#define G2_SB 72   // 64 n + 8 pad

__global__ __launch_bounds__(256) void k_gemm2(const float* __restrict__ w_out,
                                               const float* __restrict__ gamma,
                                               const float* __restrict__ beta,
                                               float* __restrict__ out) {
    __shared__ __half sA[256 * G2_SA];
    __shared__ __half sB[32 * G2_SB];
    __shared__ float s_sm[256], g_sm[256], be_sm[256];
    __shared__ float red_s[32][64];
    __shared__ float red_q[32][64];
    __shared__ float mu_s[64], rs_s[64];

    const int tid = threadIdx.x, lane = tid & 31, wid = tid >> 5;
    const int wm = wid >> 1, wn = wid & 1;
    const int n0 = blockIdx.x * 64, b = blockIdx.y;
    const uint32_t* QKp = g_QKp + (size_t)b * C_ * (N_ / 2);

    s_sm[tid]  = g_s[b * C_ + tid];
    g_sm[tid]  = gamma[tid];
    be_sm[tid] = beta[tid];
    __syncthreads();

    const int brow = tid >> 3, bnc = (tid & 7) * 8;

    float acc[4][4][4];
    #pragma unroll
    for (int i = 0; i < 4; ++i)
        #pragma unroll
        for (int j = 0; j < 4; ++j)
            #pragma unroll
            for (int e = 0; e < 4; ++e) acc[i][j][e] = 0.f;

    float4 a0, a1, a2, a3, a4, a5, a6, a7;
    uint4 bS0;
    {
        const float* wp = w_out + (size_t)tid * 256;
        a0 = *reinterpret_cast<const float4*>(wp + 0);
        a1 = *reinterpret_cast<const float4*>(wp + 4);
        a2 = *reinterpret_cast<const float4*>(wp + 8);
        a3 = *reinterpret_cast<const float4*>(wp + 12);
        a4 = *reinterpret_cast<const float4*>(wp + 16);
        a5 = *reinterpret_cast<const float4*>(wp + 20);
        a6 = *reinterpret_cast<const float4*>(wp + 24);
        a7 = *reinterpret_cast<const float4*>(wp + 28);
        bS0 = *reinterpret_cast<const uint4*>(QKp + (size_t)brow * (N_ / 2) + ((n0 + bnc) >> 1));
    }

    #pragma unroll 1
    for (int t = 0; t < 8; ++t) {
        const int kt = t * 32;
        {
            const int ao = tid * G2_SA;
            *reinterpret_cast<uint4*>(&sA[ao]) =
                make_uint4(packh(a0.x * s_sm[kt+0],  a0.y * s_sm[kt+1]),
                           packh(a0.z * s_sm[kt+2],  a0.w * s_sm[kt+3]),
                           packh(a1.x * s_sm[kt+4],  a1.y * s_sm[kt+5]),
                           packh(a1.z * s_sm[kt+6],  a1.w * s_sm[kt+7]));
            *reinterpret_cast<uint4*>(&sA[ao + 8]) =
                make_uint4(packh(a2.x * s_sm[kt+8],  a2.y * s_sm[kt+9]),
                           packh(a2.z * s_sm[kt+10], a2.w * s_sm[kt+11]),
                           packh(a3.x * s_sm[kt+12], a3.y * s_sm[kt+13]),
                           packh(a3.z * s_sm[kt+14], a3.w * s_sm[kt+15]));
            *reinterpret_cast<uint4*>(&sA[ao + 16]) =
                make_uint4(packh(a4.x * s_sm[kt+16], a4.y * s_sm[kt+17]),
                           packh(a4.z * s_sm[kt+18], a4.w * s_sm[kt+19]),
                           packh(a5.x * s_sm[kt+20], a5.y * s_sm[kt+21]),
                           packh(a5.z * s_sm[kt+22], a5.w * s_sm[kt+23]));
            *reinterpret_cast<uint4*>(&sA[ao + 24]) =
                make_uint4(packh(a6.x * s_sm[kt+24], a6.y * s_sm[kt+25]),
                           packh(a6.z * s_sm[kt+26], a6.w * s_sm[kt+27]),
                           packh(a7.x * s_sm[kt+28], a7.y * s_sm[kt+29]),
                           packh(a7.z * s_sm[kt+30], a7.w * s_sm[kt+31]));
            *reinterpret_cast<uint4*>(&sB[brow * G2_SB + bnc]) = bS0;
        }
        __syncthreads();
        if (t < 7) {
            int ktn = kt + 32;
            const float* wp = w_out + (size_t)tid * 256 + ktn;
            a0 = *reinterpret_cast<const float4*>(wp + 0);
            a1 = *reinterpret_cast<const float4*>(wp + 4);
            a2 = *reinterpret_cast<const float4*>(wp + 8);
            a3 = *reinterpret_cast<const float4*>(wp + 12);
            a4 = *reinterpret_cast<const float4*>(wp + 16);
            a5 = *reinterpret_cast<const float4*>(wp + 20);
            a6 = *reinterpret_cast<const float4*>(wp + 24);
            a7 = *reinterpret_cast<const float4*>(wp + 28);
            bS0 = *reinterpret_cast<const uint4*>(QKp + (size_t)(ktn + brow) * (N_ / 2) + ((n0 + bnc) >> 1));
        }

        #pragma unroll
        for (int k2 = 0; k2 < 2; ++k2) {
            const int k16 = k2 * 16;
            uint32_t ah[4][4];
            #pragma unroll
            for (int mf = 0; mf < 4; ++mf) {
                int rowm = wm*64 + mf*16 + (lane & 15);
                int colk = k16 + (lane >> 4) * 8;
                ldsm_x4(ah[mf][0], ah[mf][1], ah[mf][2], ah[mf][3],
                        smem_u32(sA + rowm * G2_SA + colk));
            }
            uint32_t bh[2][4];
            #pragma unroll
            for (int p = 0; p < 2; ++p) {
                int krow = k16 + (lane & 15);
                int ncol = wn*32 + p*16 + (lane >> 4) * 8;
                ldsm_x4t(bh[p][0], bh[p][1], bh[p][2], bh[p][3],
                         smem_u32(sB + krow * G2_SB + ncol));
            }
            #pragma unroll
            for (int mf = 0; mf < 4; ++mf) {
                #pragma unroll
                for (int nf = 0; nf < 4; ++nf) {
                    const int p = nf >> 1, hh = (nf & 1) * 2;
                    mma_f16(acc[mf][nf][0], acc[mf][nf][1], acc[mf][nf][2], acc[mf][nf][3],
                            ah[mf][0], ah[mf][1], ah[mf][2], ah[mf][3],
                            bh[p][hh], bh[p][hh+1]);
                }
            }
        }
        __syncthreads();
    }

    // ---- fused LayerNorm over the 256 channels this block owns ----
    #pragma unroll
    for (int nf = 0; nf < 4; ++nf)
        #pragma unroll
        for (int e = 0; e < 2; ++e) {
            float s = 0.f, q = 0.f;
            #pragma unroll
            for (int mf = 0; mf < 4; ++mf)
                #pragma unroll
                for (int rh = 0; rh < 2; ++rh) {
                    float v = acc[mf][nf][rh*2 + e];
                    s += v; q = fmaf(v, v, q);
                }
            int col = wn*32 + nf*8 + (lane & 3)*2 + e;
            red_s[wm*8 + (lane >> 2)][col] = s;
            red_q[wm*8 + (lane >> 2)][col] = q;
        }
    __syncthreads();
    if (tid < 64) {
        float s = 0.f, q = 0.f;
        #pragma unroll
        for (int r = 0; r < 32; ++r) { s += red_s[r][tid]; q += red_q[r][tid]; }
        float mu  = s * (1.f / 256.f);
        float var = q * (1.f / 256.f) - mu * mu;
        mu_s[tid] = mu;
        rs_s[tid] = rsqrtf(var + 1e-5f);
    }
    __syncthreads();

    #pragma unroll
    for (int mf = 0; mf < 4; ++mf) {
        int rbase = wm*64 + mf*16 + (lane >> 2);
        #pragma unroll
        for (int nf = 0; nf < 4; ++nf) {
            int col = wn*32 + nf*8 + (lane & 3)*2;
            #pragma unroll
            for (int rh = 0; rh < 2; ++rh) {
                int r = rbase + rh*8;
                float ga = g_sm[r], be = be_sm[r];
                float v0 = (acc[mf][nf][rh*2+0] - mu_s[col])   * rs_s[col]   * ga + be;
                float v1 = (acc[mf][nf][rh*2+1] - mu_s[col+1]) * rs_s[col+1] * ga + be;
                *reinterpret_cast<float2*>(&out[((size_t)b*C_ + r)*N_ + n0 + col]) =
                    make_float2(v0, v1);
            }
        }
    }
}

// ----------------------------------------------------------------
extern "C" void kernel_launch(void* const* d_in, const int* in_sizes, int n_in,
                              void* d_out, int out_size) {
    const float* x     = (const float*)d_in[0];
    const float* w_qkv = (const float*)d_in[1];
    const float* w_out = (const float*)d_in[2];
    const float* gamma = (const float*)d_in[3];
    const float* beta  = (const float*)d_in[4];
    float* out = (float*)d_out;

    k_gemm1<<<dim3(32, 6, 16), 256>>>(x, w_qkv);
    k_scale<<<16, 256>>>();
    k_gemm2<<<dim3(64, 16), 256>>>(w_out, gamma, beta, out);
}